// round 13
// baseline (speedup 1.0000x reference)
#include <cuda_runtime.h>
#include <math.h>
#include <stdint.h>

typedef unsigned long long ull;

#define BATCH 256
#define SEQ   128
#define VOCAB 512
#define GH    128
#define K0    65536
#define N0    1024
#define GSPLITS 9
#define TCHUNKS0 2048          /* K0/32 */

#define OFF_MU (BATCH*SEQ*VOCAB)
#define OFF_LV (OFF_MU + BATCH*GH)

// ---- scratch layout (single static __device__ array) ----
#define S_WS     0u                        /* split-K partials */
#define S_H0     (S_WS + 2359296u)         /* 256x1024 (raw, pre-BN) */
#define S_H1     (S_H0 + 262144u)          /* 256x512  (raw) */
#define S_H2B    (S_H1 + 131072u)          /* 256x256  (raw) */
#define S_HENC   (S_H2B + 65536u)          /* 256x128  */
#define S_Z      (S_HENC + 32768u)
#define S_XP     (S_Z + 32768u)            /* 256x384  */
#define S_H2ALL  (S_XP + 98304u)           /* 32768x128 */
#define S_AMP    (S_H2ALL + 4194304u)      /* 32768x4 float2 */
#define S_BNP    (S_AMP + 262144u)         /* 8 x 1024 partial sums */
#define S_BNQ    (S_BNP + 8192u)           /* 8 x 1024 partial sumsq */
#define S_TOTAL  (S_BNQ + 8192u)

__device__ float g_scratch[S_TOTAL];

// ============================================================================
// helpers
// ============================================================================
__device__ __forceinline__ uint32_t packh2(float lo, float hi) {
    uint32_t r; asm("cvt.rn.f16x2.f32 %0, %1, %2;" : "=r"(r) : "f"(hi), "f"(lo)); return r;
}

// truncation split: hi = top 11 significand bits (exact in fp16),
// lo = (v - hi) * 2048 (exact fp32 sub; fp16 keeps top 11 of remainder).
__device__ __forceinline__ void split11(float v, float& hi, float& lo) {
    hi = __uint_as_float(__float_as_uint(v) & 0xFFFFE000u);
    lo = __fmul_rn(__fsub_rn(v, hi), 2048.0f);
}

__device__ __forceinline__ float bnl(float x, float s, float h) {
    float o = fmaf(x, s, h);
    return o > 0.f ? o : 0.01f * o;
}

#define MMA_F16(acc, af, bf) asm volatile( \
    "mma.sync.aligned.m16n8k16.row.col.f32.f16.f16.f32 " \
    "{%0,%1,%2,%3}, {%4,%5,%6,%7}, {%8,%9}, {%0,%1,%2,%3};" \
    : "+f"((acc)[0]), "+f"((acc)[1]), "+f"((acc)[2]), "+f"((acc)[3]) \
    : "r"((af)[0]), "r"((af)[1]), "r"((af)[2]), "r"((af)[3]), \
      "r"((bf)[0]), "r"((bf)[1]))

#define PSTRIDE 20
#define PLANE   (128 * PSTRIDE)
#define BUFU32  (4 * PLANE)                /* 10240 u32 per buffer */
#define MMA_SMEM (2 * BUFU32 * 4 + 8192)   /* buffers + scale/shift = 90112 B */
#define LOGITS_SMEM (16 * PLANE * 4 + 4096)

// ============================================================================
// FP16-split tensor GEMM via mma.sync m16n8k16, tile 128x128, BK=32.
//   optional fused BN+LeakyReLU on A columns: scale/shift finalized IN-KERNEL
//   from partial sums (ps/pss, 8 parts) + gamma/beta — into smem tables.
//   nsplit>1 -> partials at C + z*splitStride; nsplit==1 -> direct (+bias/relu)
// ============================================================================
__global__ __launch_bounds__(256, 1) void gemm_mma(const float* __restrict__ A,
        const float* __restrict__ B, const float* __restrict__ bias,
        float* __restrict__ C, int ldA, int ldc, int tchunks, int nsplit,
        size_t splitStride, const float* __restrict__ ps,
        const float* __restrict__ pss, const float* __restrict__ gw,
        const float* __restrict__ bw, int act) {
    extern __shared__ float smf[];
    uint32_t* smu = (uint32_t*)smf;
    float* sscale = smf + 20480;
    float* sshift = smf + 20480 + 1024;
    const int tid  = threadIdx.x;
    const int lane = tid & 31;
    const int g    = lane >> 2;
    const int t    = lane & 3;
    const int warp = tid >> 5;
    const int m0w  = (warp >> 2) * 64;
    const int n0w  = (warp & 3) * 32;
    const int n0   = blockIdx.x * 128;
    const int m0   = blockIdx.y * 128;

    const bool hasBN = (ps != nullptr);
    if (hasBN) {
        for (int f = tid; f < ldA; f += 256) {
            float s = 0.f, ss2 = 0.f;
            #pragma unroll
            for (int p = 0; p < 8; p++) { s += ps[p*ldA+f]; ss2 += pss[p*ldA+f]; }
            float mean = s * (1.0f / BATCH);
            float var = ss2 * (1.0f / BATCH) - mean * mean;
            float sc = rsqrtf(var + 1e-5f) * gw[f];
            sscale[f] = sc;
            sshift[f] = bw[f] - mean * sc;
        }
        __syncthreads();
    }

    const int cs = (int)(((long long)blockIdx.z * tchunks) / nsplit);
    const int ce = (int)(((long long)(blockIdx.z + 1) * tchunks) / nsplit);
    const int nchunks = ce - cs;
    const int kbase = cs * 32;

    const int rb = tid >> 3;
    const int q  = tid & 7;

    float accH[4][4][4], accL[4][4][4];
    #pragma unroll
    for (int mt = 0; mt < 4; mt++)
        #pragma unroll
        for (int nt = 0; nt < 4; nt++)
            #pragma unroll
            for (int i = 0; i < 4; i++) { accH[mt][nt][i] = 0.f; accL[mt][nt][i] = 0.f; }

    float4 stA[4], stB[4];

    {
        int f = kbase + q*4;
        float4 sc4, sh4;
        if (hasBN) { sc4 = *(float4*)&sscale[f]; sh4 = *(float4*)&sshift[f]; }
        #pragma unroll
        for (int j = 0; j < 4; j++) {
            stA[j] = *(const float4*)&A[(size_t)(m0 + rb + 32*j) * ldA + f];
            if (hasBN) {
                stA[j].x = bnl(stA[j].x, sc4.x, sh4.x);
                stA[j].y = bnl(stA[j].y, sc4.y, sh4.y);
                stA[j].z = bnl(stA[j].z, sc4.z, sh4.z);
                stA[j].w = bnl(stA[j].w, sc4.w, sh4.w);
            }
            stB[j] = *(const float4*)&B[(size_t)(n0 + rb + 32*j) * ldA + f];
        }
    }
    {
        uint32_t* ahi = smu;           uint32_t* alo = smu + PLANE;
        uint32_t* bhi = smu + 2*PLANE; uint32_t* blo = smu + 3*PLANE;
        #pragma unroll
        for (int j = 0; j < 4; j++) {
            int off = (rb + 32*j) * PSTRIDE + 2*q;
            float4 v = stA[j];
            float hx,lx,hy,ly,hz,lz,hw,lw;
            split11(v.x,hx,lx); split11(v.y,hy,ly); split11(v.z,hz,lz); split11(v.w,hw,lw);
            *(uint2*)&ahi[off] = make_uint2(packh2(hx,hy), packh2(hz,hw));
            *(uint2*)&alo[off] = make_uint2(packh2(lx,ly), packh2(lz,lw));
            v = stB[j];
            split11(v.x,hx,lx); split11(v.y,hy,ly); split11(v.z,hz,lz); split11(v.w,hw,lw);
            *(uint2*)&bhi[off] = make_uint2(packh2(hx,hy), packh2(hz,hw));
            *(uint2*)&blo[off] = make_uint2(packh2(lx,ly), packh2(lz,lw));
        }
    }
    __syncthreads();

    for (int c = 0; c < nchunks; c++) {
        if (c + 1 < nchunks) {
            int kp = kbase + (c + 1) * 32 + q*4;
            float4 sc4, sh4;
            if (hasBN) { sc4 = *(float4*)&sscale[kp - kbase - (c+1)*32 + (c+1)*32 + kbase - kbase + q*0 + kp - q*4 + q*4 - kp + kp]; }
            // (compute below without the confusing expression)
            if (hasBN) { sc4 = *(float4*)&sscale[kp]; sh4 = *(float4*)&sshift[kp]; }
            #pragma unroll
            for (int j = 0; j < 4; j++) {
                stA[j] = *(const float4*)&A[(size_t)(m0 + rb + 32*j) * ldA + kp];
                if (hasBN) {
                    stA[j].x = bnl(stA[j].x, sc4.x, sh4.x);
                    stA[j].y = bnl(stA[j].y, sc4.y, sh4.y);
                    stA[j].z = bnl(stA[j].z, sc4.z, sh4.z);
                    stA[j].w = bnl(stA[j].w, sc4.w, sh4.w);
                }
                stB[j] = *(const float4*)&B[(size_t)(n0 + rb + 32*j) * ldA + kp];
            }
        }

        const uint32_t* base = smu + (c & 1) * BUFU32;
        const uint32_t* pAhi = base;
        const uint32_t* pAlo = base + PLANE;
        const uint32_t* pBhi = base + 2*PLANE;
        const uint32_t* pBlo = base + 3*PLANE;

        #pragma unroll
        for (int ks = 0; ks < 2; ks++) {
            const int kk = ks * 8;
            uint32_t aH[4][4], aL[4][4], bH[4][2], bL[4][2];
            #pragma unroll
            for (int mt = 0; mt < 4; mt++) {
                int ro = (m0w + mt*16 + g) * PSTRIDE + kk + t;
                aH[mt][0] = pAhi[ro];
                aH[mt][1] = pAhi[ro + 8*PSTRIDE];
                aH[mt][2] = pAhi[ro + 4];
                aH[mt][3] = pAhi[ro + 8*PSTRIDE + 4];
                aL[mt][0] = pAlo[ro];
                aL[mt][1] = pAlo[ro + 8*PSTRIDE];
                aL[mt][2] = pAlo[ro + 4];
                aL[mt][3] = pAlo[ro + 8*PSTRIDE + 4];
            }
            #pragma unroll
            for (int nt = 0; nt < 4; nt++) {
                int rn = (n0w + nt*8 + g) * PSTRIDE + kk + t;
                bH[nt][0] = pBhi[rn];
                bH[nt][1] = pBhi[rn + 4];
                bL[nt][0] = pBlo[rn];
                bL[nt][1] = pBlo[rn + 4];
            }
            #pragma unroll
            for (int mt = 0; mt < 4; mt++)
                #pragma unroll
                for (int nt = 0; nt < 4; nt++) {
                    MMA_F16(accH[mt][nt], aH[mt], bH[nt]);
                    MMA_F16(accL[mt][nt], aH[mt], bL[nt]);
                    MMA_F16(accL[mt][nt], aL[mt], bH[nt]);
                }
        }

        if (c + 1 < nchunks) {
            uint32_t* bb = smu + ((c + 1) & 1) * BUFU32;
            uint32_t* ahi = bb;           uint32_t* alo = bb + PLANE;
            uint32_t* bhi = bb + 2*PLANE; uint32_t* blo = bb + 3*PLANE;
            #pragma unroll
            for (int j = 0; j < 4; j++) {
                int off = (rb + 32*j) * PSTRIDE + 2*q;
                float4 v = stA[j];
                float hx,lx,hy,ly,hz,lz,hw,lw;
                split11(v.x,hx,lx); split11(v.y,hy,ly); split11(v.z,hz,lz); split11(v.w,hw,lw);
                *(uint2*)&ahi[off] = make_uint2(packh2(hx,hy), packh2(hz,hw));
                *(uint2*)&alo[off] = make_uint2(packh2(lx,ly), packh2(lz,lw));
                v = stB[j];
                split11(v.x,hx,lx); split11(v.y,hy,ly); split11(v.z,hz,lz); split11(v.w,hw,lw);
                *(uint2*)&bhi[off] = make_uint2(packh2(hx,hy), packh2(hz,hw));
                *(uint2*)&blo[off] = make_uint2(packh2(lx,ly), packh2(lz,lw));
            }
        }
        __syncthreads();
    }

    const float inv2048 = 1.0f / 2048.0f;
    float* Cp = C + (size_t)blockIdx.z * splitStride;
    #pragma unroll
    for (int mt = 0; mt < 4; mt++) {
        #pragma unroll
        for (int nt = 0; nt < 4; nt++) {
            int row = m0 + m0w + mt*16 + g;
            int col = n0 + n0w + nt*8 + 2*t;
            float o0 = accH[mt][nt][0] + accL[mt][nt][0]*inv2048;
            float o1 = accH[mt][nt][1] + accL[mt][nt][1]*inv2048;
            float o2 = accH[mt][nt][2] + accL[mt][nt][2]*inv2048;
            float o3 = accH[mt][nt][3] + accL[mt][nt][3]*inv2048;
            if (bias) {
                float bx = bias[col], by = bias[col+1];
                o0 += bx; o1 += by; o2 += bx; o3 += by;
            }
            if (act) {
                o0 = fmaxf(o0, 0.f); o1 = fmaxf(o1, 0.f);
                o2 = fmaxf(o2, 0.f); o3 = fmaxf(o3, 0.f);
            }
            *(float2*)&Cp[(size_t)row * ldc + col] = make_float2(o0, o1);
            *(float2*)&Cp[(size_t)(row + 8) * ldc + col] = make_float2(o2, o3);
        }
    }
}

// ============================================================================
// Persistent logits GEMM: A[32768,128] @ Wfc[512,128]^T + bias, fused argmax.
// grid (4, 32): each CTA owns 128 cols, converts B ONCE, loops 8 m-tiles.
// ============================================================================
__global__ __launch_bounds__(256, 1) void gemm_logits(const float* __restrict__ A,
        const float* __restrict__ B, const float* __restrict__ bias,
        float2* __restrict__ amax) {
    extern __shared__ float smf[];
    uint32_t* smu = (uint32_t*)smf;
    float2* sred = (float2*)(smf + 16 * PLANE);
    const int tid  = threadIdx.x;
    const int lane = tid & 31;
    const int g    = lane >> 2;
    const int t    = lane & 3;
    const int warp = tid >> 5;
    const int m0w  = (warp >> 2) * 64;
    const int n0w  = (warp & 3) * 32;
    const int n0   = blockIdx.x * 128;
    const int warp_n = warp & 3;
    const int rb = tid >> 3;
    const int q  = tid & 7;
    const float inv2048 = 1.0f / 2048.0f;

    #pragma unroll
    for (int c = 0; c < 4; c++) {
        uint32_t* bhi = smu + (8 + c*2) * PLANE;
        uint32_t* blo = smu + (9 + c*2) * PLANE;
        #pragma unroll
        for (int j = 0; j < 4; j++) {
            int row = rb + 32*j;
            float4 v = *(const float4*)&B[(size_t)(n0 + row) * GH + c*32 + q*4];
            float hx,lx,hy,ly,hz,lz,hw,lw;
            split11(v.x,hx,lx); split11(v.y,hy,ly); split11(v.z,hz,lz); split11(v.w,hw,lw);
            int off = row * PSTRIDE + 2*q;
            *(uint2*)&bhi[off] = make_uint2(packh2(hx,hy), packh2(hz,hw));
            *(uint2*)&blo[off] = make_uint2(packh2(lx,ly), packh2(lz,lw));
        }
    }
    __syncthreads();

    for (int mi = 0; mi < 8; mi++) {
        const int m0 = (blockIdx.y * 8 + mi) * 128;

        #pragma unroll
        for (int c = 0; c < 4; c++) {
            uint32_t* ahi = smu + (c*2) * PLANE;
            uint32_t* alo = smu + (c*2 + 1) * PLANE;
            #pragma unroll
            for (int j = 0; j < 4; j++) {
                int row = rb + 32*j;
                float4 v = *(const float4*)&A[(size_t)(m0 + row) * GH + c*32 + q*4];
                float hx,lx,hy,ly,hz,lz,hw,lw;
                split11(v.x,hx,lx); split11(v.y,hy,ly); split11(v.z,hz,lz); split11(v.w,hw,lw);
                int off = row * PSTRIDE + 2*q;
                *(uint2*)&ahi[off] = make_uint2(packh2(hx,hy), packh2(hz,hw));
                *(uint2*)&alo[off] = make_uint2(packh2(lx,ly), packh2(lz,lw));
            }
        }
        __syncthreads();

        float accH[4][4][4], accL[4][4][4];
        #pragma unroll
        for (int mt = 0; mt < 4; mt++)
            #pragma unroll
            for (int nt = 0; nt < 4; nt++)
                #pragma unroll
                for (int i = 0; i < 4; i++) { accH[mt][nt][i] = 0.f; accL[mt][nt][i] = 0.f; }

        #pragma unroll
        for (int c = 0; c < 4; c++) {
            const uint32_t* pAhi = smu + (c*2) * PLANE;
            const uint32_t* pAlo = smu + (c*2 + 1) * PLANE;
            const uint32_t* pBhi = smu + (8 + c*2) * PLANE;
            const uint32_t* pBlo = smu + (9 + c*2) * PLANE;
            #pragma unroll
            for (int ks = 0; ks < 2; ks++) {
                const int kk = ks * 8;
                uint32_t aH[4][4], aL[4][4], bH[4][2], bL[4][2];
                #pragma unroll
                for (int mt = 0; mt < 4; mt++) {
                    int ro = (m0w + mt*16 + g) * PSTRIDE + kk + t;
                    aH[mt][0] = pAhi[ro];
                    aH[mt][1] = pAhi[ro + 8*PSTRIDE];
                    aH[mt][2] = pAhi[ro + 4];
                    aH[mt][3] = pAhi[ro + 8*PSTRIDE + 4];
                    aL[mt][0] = pAlo[ro];
                    aL[mt][1] = pAlo[ro + 8*PSTRIDE];
                    aL[mt][2] = pAlo[ro + 4];
                    aL[mt][3] = pAlo[ro + 8*PSTRIDE + 4];
                }
                #pragma unroll
                for (int nt = 0; nt < 4; nt++) {
                    int rn = (n0w + nt*8 + g) * PSTRIDE + kk + t;
                    bH[nt][0] = pBhi[rn];
                    bH[nt][1] = pBhi[rn + 4];
                    bL[nt][0] = pBlo[rn];
                    bL[nt][1] = pBlo[rn + 4];
                }
                #pragma unroll
                for (int mt = 0; mt < 4; mt++)
                    #pragma unroll
                    for (int nt = 0; nt < 4; nt++) {
                        MMA_F16(accH[mt][nt], aH[mt], bH[nt]);
                        MMA_F16(accL[mt][nt], aH[mt], bL[nt]);
                        MMA_F16(accL[mt][nt], aL[mt], bH[nt]);
                    }
            }
        }

        #pragma unroll
        for (int half = 0; half < 2; half++) {
            #pragma unroll
            for (int mt = 0; mt < 4; mt++) {
                int rloc = m0w + mt*16 + g + half*8;
                float best = -1e30f; int bidx = 0;
                #pragma unroll
                for (int nt = 0; nt < 4; nt++) {
                    #pragma unroll
                    for (int e = 0; e < 2; e++) {
                        int col = n0 + n0w + nt*8 + 2*t + e;
                        float v = accH[mt][nt][half*2 + e] + accL[mt][nt][half*2 + e]*inv2048
                                  + bias[col];
                        if (v > best) { best = v; bidx = col; }
                    }
                }
                #pragma unroll
                for (int o = 1; o < 4; o <<= 1) {
                    float ov = __shfl_xor_sync(0xffffffffu, best, o);
                    int   oi = __shfl_xor_sync(0xffffffffu, bidx, o);
                    if (ov > best || (ov == best && oi < bidx)) { best = ov; bidx = oi; }
                }
                if (t == 0) sred[rloc * 4 + warp_n] = make_float2(best, __int_as_float(bidx));
            }
        }
        __syncthreads();
        if (tid < 128) {
            float best = -1e30f; int bidx = 0x7fffffff;
            #pragma unroll
            for (int wn = 0; wn < 4; wn++) {
                float2 e = sred[tid * 4 + wn];
                int ei = __float_as_int(e.y);
                if (e.x > best || (e.x == best && ei < bidx)) { best = e.x; bidx = ei; }
            }
            amax[(size_t)(m0 + tid) * 4 + blockIdx.x] = make_float2(best, __int_as_float(bidx));
        }
        __syncthreads();
    }
}

// ============================================================================
// fused split-K reduce + bias + BN partial stats (same order as before)
// grid (N/256, 8); thread = feature, part = 32 batch rows
// ============================================================================
__global__ __launch_bounds__(256) void reduce_bn(const float* __restrict__ ws,
        const float* __restrict__ bias, float* __restrict__ outH,
        float* __restrict__ ps, float* __restrict__ pss, int nsplit, int N) {
    int f = blockIdx.x * 256 + threadIdx.x;
    int part = blockIdx.y;
    float bb = bias[f];
    float s = 0.f, ss = 0.f;
    int b0 = part * 32;
    for (int b = b0; b < b0 + 32; b++) {
        float v = 0.f;
        for (int sp = 0; sp < nsplit; sp++)
            v += ws[(size_t)sp * ((size_t)BATCH * N) + (size_t)b * N + f];
        v += bb;
        outH[(size_t)b * N + f] = v;
        s += v; ss += v * v;
    }
    ps[part * N + f] = s;
    pss[part * N + f] = ss;
}

// generic deterministic split-K reduce + bias (+optional relu)
__global__ __launch_bounds__(256) void reduce_gen(const float* __restrict__ ws,
        const float* __restrict__ bias, float* __restrict__ out,
        int nsplit, int strideElems, int nmask, int act) {
    int i = blockIdx.x * 256 + threadIdx.x;
    float s = 0.0f;
    for (int sp = 0; sp < nsplit; sp++) s += ws[(size_t)sp * strideElems + i];
    s += bias[i & nmask];
    if (act) s = fmaxf(s, 0.f);
    out[i] = s;
}

// ============================================================================
// fp32x2 helpers + small GEMMs
// ============================================================================
__device__ __forceinline__ void fma2(ull &d, ull a, ull b) {
    asm("fma.rn.f32x2 %0, %1, %2, %0;" : "+l"(d) : "l"(a), "l"(b));
}
__device__ __forceinline__ ull pk2(float x, float y) {
    ull d; asm("mov.b64 %0, {%1, %2};" : "=l"(d) : "f"(x), "f"(y)); return d;
}
__device__ __forceinline__ float2 unpk2(ull d) {
    float2 r; asm("mov.b64 {%0, %1}, %2;" : "=f"(r.x), "=f"(r.y) : "l"(d)); return r;
}

// xp projection: C[M,N] = A[M,K] @ W[N,K]^T + bias
__global__ __launch_bounds__(256) void gemm_kernel(const float* __restrict__ A,
        const float* __restrict__ W, const float* __restrict__ bias,
        float* __restrict__ C, int M, int N, int K) {
    __shared__ float As[16][68];
    __shared__ float Bs[16][68];
    const int tid = threadIdx.x;
    const int n0 = blockIdx.x * 64;
    const int m0 = blockIdx.y * 64;
    const int trow = tid >> 4;
    const int tcol = tid & 15;
    const int lm = tid >> 2;
    const int lk = (tid & 3) * 4;

    ull acc[4][2];
    #pragma unroll
    for (int r = 0; r < 4; r++) { acc[r][0] = 0ull; acc[r][1] = 0ull; }

    for (int kk = 0; kk < K; kk += 16) {
        float4 va = *(const float4*)&A[(size_t)(m0 + lm) * K + kk + lk];
        float4 vb = *(const float4*)&W[(size_t)(n0 + lm) * K + kk + lk];
        As[lk+0][lm] = va.x; As[lk+1][lm] = va.y; As[lk+2][lm] = va.z; As[lk+3][lm] = va.w;
        Bs[lk+0][lm] = vb.x; Bs[lk+1][lm] = vb.y; Bs[lk+2][lm] = vb.z; Bs[lk+3][lm] = vb.w;
        __syncthreads();
        #pragma unroll
        for (int k = 0; k < 16; k++) {
            float4 a = *(const float4*)&As[k][trow * 4];
            const ull* bp = (const ull*)&Bs[k][tcol * 4];
            ull b0 = bp[0], b1 = bp[1];
            ull a0 = pk2(a.x, a.x), a1 = pk2(a.y, a.y);
            ull a2 = pk2(a.z, a.z), a3 = pk2(a.w, a.w);
            fma2(acc[0][0], a0, b0); fma2(acc[0][1], a0, b1);
            fma2(acc[1][0], a1, b0); fma2(acc[1][1], a1, b1);
            fma2(acc[2][0], a2, b0); fma2(acc[2][1], a2, b1);
            fma2(acc[3][0], a3, b0); fma2(acc[3][1], a3, b1);
        }
        __syncthreads();
    }

    #pragma unroll
    for (int r = 0; r < 4; r++) {
        int m = m0 + trow * 4 + r;
        int n = n0 + tcol * 4;
        float2 v0 = unpk2(acc[r][0]);
        float2 v1 = unpk2(acc[r][1]);
        *(float4*)&C[(size_t)m * N + n] = make_float4(v0.x + bias[n+0], v0.y + bias[n+1],
                                                      v1.x + bias[n+2], v1.y + bias[n+3]);
    }
}

// mu & lv in one CTA + fused reparameterization + output writes
__global__ __launch_bounds__(256) void gemm_mulv(const float* __restrict__ A,
        const float* __restrict__ Wmu, const float* __restrict__ bmu,
        const float* __restrict__ Wlv, const float* __restrict__ blv,
        const float* __restrict__ eps, float* __restrict__ z,
        float* __restrict__ out) {
    __shared__ float As[16][68];
    __shared__ float Bm[16][68];
    __shared__ float Bl[16][68];
    const int tid = threadIdx.x;
    const int n0 = blockIdx.x * 64;
    const int m0 = blockIdx.y * 64;
    const int trow = tid >> 4;
    const int tcol = tid & 15;
    const int lm = tid >> 2;
    const int lk = (tid & 3) * 4;

    ull am[4][2], al[4][2];
    #pragma unroll
    for (int r = 0; r < 4; r++) { am[r][0]=0ull; am[r][1]=0ull; al[r][0]=0ull; al[r][1]=0ull; }

    for (int kk = 0; kk < GH; kk += 16) {
        float4 va = *(const float4*)&A[(size_t)(m0 + lm) * GH + kk + lk];
        float4 vm = *(const float4*)&Wmu[(size_t)(n0 + lm) * GH + kk + lk];
        float4 vl = *(const float4*)&Wlv[(size_t)(n0 + lm) * GH + kk + lk];
        As[lk+0][lm] = va.x; As[lk+1][lm] = va.y; As[lk+2][lm] = va.z; As[lk+3][lm] = va.w;
        Bm[lk+0][lm] = vm.x; Bm[lk+1][lm] = vm.y; Bm[lk+2][lm] = vm.z; Bm[lk+3][lm] = vm.w;
        Bl[lk+0][lm] = vl.x; Bl[lk+1][lm] = vl.y; Bl[lk+2][lm] = vl.z; Bl[lk+3][lm] = vl.w;
        __syncthreads();
        #pragma unroll
        for (int k = 0; k < 16; k++) {
            float4 a = *(const float4*)&As[k][trow * 4];
            const ull* bmp = (const ull*)&Bm[k][tcol * 4];
            const ull* blp = (const ull*)&Bl[k][tcol * 4];
            ull bm0 = bmp[0], bm1 = bmp[1], bl0 = blp[0], bl1 = blp[1];
            ull a0 = pk2(a.x, a.x), a1 = pk2(a.y, a.y);
            ull a2 = pk2(a.z, a.z), a3 = pk2(a.w, a.w);
            fma2(am[0][0], a0, bm0); fma2(am[0][1], a0, bm1);
            fma2(am[1][0], a1, bm0); fma2(am[1][1], a1, bm1);
            fma2(am[2][0], a2, bm0); fma2(am[2][1], a2, bm1);
            fma2(am[3][0], a3, bm0); fma2(am[3][1], a3, bm1);
            fma2(al[0][0], a0, bl0); fma2(al[0][1], a0, bl1);
            fma2(al[1][0], a1, bl0); fma2(al[1][1], a1, bl1);
            fma2(al[2][0], a2, bl0); fma2(al[2][1], a2, bl1);
            fma2(al[3][0], a3, bl0); fma2(al[3][1], a3, bl1);
        }
        __syncthreads();
    }

    #pragma unroll
    for (int r = 0; r < 4; r++) {
        int m = m0 + trow * 4 + r;
        int n = n0 + tcol * 4;
        size_t idx = (size_t)m * GH + n;
        float2 m0v = unpk2(am[r][0]);
        float2 m1v = unpk2(am[r][1]);
        float2 l0v = unpk2(al[r][0]);
        float2 l1v = unpk2(al[r][1]);
        float mu0 = m0v.x + bmu[n+0], mu1 = m0v.y + bmu[n+1];
        float mu2 = m1v.x + bmu[n+2], mu3 = m1v.y + bmu[n+3];
        float lv0 = l0v.x + blv[n+0], lv1 = l0v.y + blv[n+1];
        float lv2 = l1v.x + blv[n+2], lv3 = l1v.y + blv[n+3];
        float4 ev = *(const float4*)&eps[idx];
        *(float4*)&out[OFF_MU + idx] = make_float4(mu0, mu1, mu2, mu3);
        *(float4*)&out[OFF_LV + idx] = make_float4(lv0, lv1, lv2, lv3);
        *(float4*)&z[idx] = make_float4(mu0 + ev.x * expf(0.5f * lv0),
                                        mu1 + ev.y * expf(0.5f * lv1),
                                        mu2 + ev.z * expf(0.5f * lv2),
                                        mu3 + ev.w * expf(0.5f * lv3));
    }
}

// ============================================================================
// GRU recurrence: 128 CTAs x 384 thr, 2 rows/CTA, register weights + f32x2
// ============================================================================
__global__ __launch_bounds__(384, 1) void gru_kernel(const float* __restrict__ xp,
        const float* __restrict__ Whh, const float* __restrict__ bhh,
        float* __restrict__ h2all) {
    __shared__ __align__(16) float h_a[128];
    __shared__ __align__(16) float h_b[128];
    __shared__ float hp_s[768];
    __shared__ float xp_s[768];
    const int j = threadIdx.x;
    const int row0 = blockIdx.x * 2;

    ull w2[64];
    #pragma unroll
    for (int kq = 0; kq < 32; kq++) {
        float4 v = *(const float4*)&Whh[(size_t)j * GH + kq * 4];
        w2[2*kq+0] = pk2(v.x, v.y);
        w2[2*kq+1] = pk2(v.z, v.w);
    }
    const float bh = bhh[j];
    xp_s[j]       = xp[(size_t)row0 * 384 + j];
    xp_s[384 + j] = xp[(size_t)(row0 + 1) * 384 + j];
    if (j < 128) { h_a[j] = 0.0f; h_b[j] = 0.0f; }
    __syncthreads();

    for (int t = 0; t < SEQ; t++) {
        ull accA = 0ull, accB = 0ull;
        #pragma unroll
        for (int kq = 0; kq < 32; kq++) {
            ulonglong2 ha = *(const ulonglong2*)&h_a[kq * 4];
            ulonglong2 hb = *(const ulonglong2*)&h_b[kq * 4];
            fma2(accA, w2[2*kq+0], ha.x);
            fma2(accA, w2[2*kq+1], ha.y);
            fma2(accB, w2[2*kq+0], hb.x);
            fma2(accB, w2[2*kq+1], hb.y);
        }
        float2 pa = unpk2(accA);
        float2 pb = unpk2(accB);
        hp_s[j]       = pa.x + pa.y + bh;
        hp_s[384 + j] = pb.x + pb.y + bh;
        __syncthreads();
        if (j < 256) {
            int r = j >> 7, u = j & 127;
            const float* hp = hp_s + r * 384;
            const float* xq = xp_s + r * 384;
            float rg = 1.0f / (1.0f + expf(-(xq[u]       + hp[u])));
            float zg = 1.0f / (1.0f + expf(-(xq[128 + u] + hp[128 + u])));
            float nn = tanhf(xq[256 + u] + rg * hp[256 + u]);
            float hold = r ? h_b[u] : h_a[u];
            float hnew = (1.0f - zg) * nn + zg * hold;
            if (r) h_b[u] = hnew; else h_a[u] = hnew;
            h2all[((size_t)t * BATCH + row0 + r) * GH + u] = hnew;
        }
        __syncthreads();
    }
}

// ============================================================================
// final argmax reduce over 4 partials + one-hot write
// ============================================================================
__global__ __launch_bounds__(256) void argmax_final(const float2* __restrict__ amp,
                                                    float* __restrict__ out) {
    int row  = blockIdx.x * 8 + (threadIdx.x >> 5);
    int lane = threadIdx.x & 31;
    float best = -1e30f; int bi = 0x7fffffff;
    if (lane < 4) {
        float2 e = amp[(size_t)row * 4 + lane];
        best = e.x; bi = __float_as_int(e.y);
    }
    #pragma unroll
    for (int o = 1; o < 4; o <<= 1) {
        float ov = __shfl_xor_sync(0xffffffffu, best, o);
        int   oi = __shfl_xor_sync(0xffffffffu, bi, o);
        if (ov > best || (ov == best && oi < bi)) { best = ov; bi = oi; }
    }
    bi = __shfl_sync(0xffffffffu, bi, 0);
    int t = row >> 8, b = row & 255;
    float* op = out + (size_t)b * (SEQ * VOCAB) + (size_t)t * VOCAB;
    #pragma unroll
    for (int q = 0; q < 4; q++) {
        int c = lane * 16 + q * 4;
        *(float4*)&op[c] = make_float4(c == bi ? 1.f : 0.f, c + 1 == bi ? 1.f : 0.f,
                                       c + 2 == bi ? 1.f : 0.f, c + 3 == bi ? 1.f : 0.f);
    }
}

// ============================================================================
// launcher
// ============================================================================
extern "C" void kernel_launch(void* const* d_in, const int* in_sizes, int n_in,
                              void* d_out, int out_size) {
    (void)in_sizes; (void)n_in; (void)out_size;
    const float* x    = (const float*)d_in[0];
    const float* eps  = (const float*)d_in[1];
    const float* W0   = (const float*)d_in[2];
    const float* b0   = (const float*)d_in[3];
    const float* g0   = (const float*)d_in[4];
    const float* be0  = (const float*)d_in[5];
    const float* W1   = (const float*)d_in[6];
    const float* b1   = (const float*)d_in[7];
    const float* g1   = (const float*)d_in[8];
    const float* be1  = (const float*)d_in[9];
    const float* W2   = (const float*)d_in[10];
    const float* b2   = (const float*)d_in[11];
    const float* g2   = (const float*)d_in[12];
    const float* be2  = (const float*)d_in[13];
    const float* Wout = (const float*)d_in[14];
    const float* bout = (const float*)d_in[15];
    const float* Wmu  = (const float*)d_in[16];
    const float* bmu  = (const float*)d_in[17];
    const float* Wlv  = (const float*)d_in[18];
    const float* blv  = (const float*)d_in[19];
    const float* Wih  = (const float*)d_in[20];
    const float* bih  = (const float*)d_in[21];
    const float* Whh  = (const float*)d_in[22];
    const float* bhh  = (const float*)d_in[23];
    const float* Wfc  = (const float*)d_in[24];
    const float* bfc  = (const float*)d_in[25];
    float* out = (float*)d_out;

    float* S = nullptr;
    cudaGetSymbolAddress((void**)&S, g_scratch);

    cudaFuncSetAttribute(gemm_mma, cudaFuncAttributeMaxDynamicSharedMemorySize, MMA_SMEM);
    cudaFuncSetAttribute(gemm_logits, cudaFuncAttributeMaxDynamicSharedMemorySize, LOGITS_SMEM);

    // --- encoder layer 0: fp16-split mma, split-K=9 (144 CTAs = 1 wave) ---
    gemm_mma<<<dim3(8, 2, GSPLITS), 256, MMA_SMEM>>>(x, W0, nullptr, S + S_WS,
        K0, N0, TCHUNKS0, GSPLITS, (size_t)BATCH * N0,
        nullptr, nullptr, nullptr, nullptr, 0);
    reduce_bn<<<dim3(4, 8), 256>>>(S + S_WS, b0, S + S_H0, S + S_BNP, S + S_BNQ,
                                   GSPLITS, 1024);

    // --- encoder layer 1: 1024 -> 512, split-K=16 (BN0+lrelu finalized in-kernel) ---
    gemm_mma<<<dim3(4, 2, 16), 256, MMA_SMEM>>>(S + S_H0, W1, nullptr, S + S_WS,
        1024, 512, 32, 16, (size_t)BATCH * 512,
        S + S_BNP, S + S_BNQ, g0, be0, 0);
    reduce_bn<<<dim3(2, 8), 256>>>(S + S_WS, b1, S + S_H1, S + S_BNP, S + S_BNQ,
                                   16, 512);

    // --- encoder layer 2: 512 -> 256, split-K=8 (BN1 fused) ---
    gemm_mma<<<dim3(2, 2, 8), 256, MMA_SMEM>>>(S + S_H1, W2, nullptr, S + S_WS,
        512, 256, 16, 8, (size_t)BATCH * 256,
        S + S_BNP, S + S_BNQ, g1, be1, 0);
    reduce_bn<<<dim3(1, 8), 256>>>(S + S_WS, b2, S + S_H2B, S + S_BNP, S + S_BNQ,
                                   8, 256);

    // --- out layer: 256 -> 128, split-K=8 (BN2 fused), relu in reduce ---
    gemm_mma<<<dim3(1, 2, 8), 256, MMA_SMEM>>>(S + S_H2B, Wout, nullptr, S + S_WS,
        256, 128, 8, 8, (size_t)BATCH * 128,
        S + S_BNP, S + S_BNQ, g2, be2, 0);
    reduce_gen<<<128, 256>>>(S + S_WS, bout, S + S_HENC, 8, BATCH * 128, 127, 1);

    // --- mu & lv & reparameterize in ONE kernel (writes out mu/lv + z) ---
    gemm_mulv<<<dim3(2, 4), 256>>>(S + S_HENC, Wmu, bmu, Wlv, blv, eps, S + S_Z, out);

    // --- GRU input projection ---
    gemm_kernel<<<dim3(6, 4), 256>>>(S + S_Z, Wih, bih, S + S_XP, 256, 384, 128);

    // --- GRU recurrence ---
    gru_kernel<<<128, 384>>>(S + S_XP, Whh, bhh, S + S_H2ALL);

    // --- persistent logits GEMM with fused bias+argmax (1 wave) ---
    gemm_logits<<<dim3(4, 32), 256, LOGITS_SMEM>>>(S + S_H2ALL, Wfc, bfc,
                                                   (float2*)(S + S_AMP));
    argmax_final<<<4096, 256>>>((const float2*)(S + S_AMP), out);
}

// round 14
// speedup vs baseline: 1.0888x; 1.0888x over previous
#include <cuda_runtime.h>
#include <math.h>
#include <stdint.h>

typedef unsigned long long ull;

#define BATCH 256
#define SEQ   128
#define VOCAB 512
#define GH    128
#define K0    65536
#define N0    1024
#define GSPLITS 9
#define TCHUNKS0 2048          /* K0/32 */

#define OFF_MU (BATCH*SEQ*VOCAB)
#define OFF_LV (OFF_MU + BATCH*GH)

// ---- scratch layout (single static __device__ array) ----
#define S_WS     0u                        /* split-K partials */
#define S_H0     (S_WS + 2359296u)         /* 256x1024 (raw, pre-BN) */
#define S_H1     (S_H0 + 262144u)          /* 256x512  (raw) */
#define S_H2B    (S_H1 + 131072u)          /* 256x256  (raw) */
#define S_HENC   (S_H2B + 65536u)          /* 256x128  */
#define S_Z      (S_HENC + 32768u)
#define S_XP     (S_Z + 32768u)            /* 256x384  */
#define S_H2ALL  (S_XP + 98304u)           /* 32768x128 */
#define S_AMP    (S_H2ALL + 4194304u)      /* 32768x4 float2 */
#define S_BNP    (S_AMP + 262144u)         /* 8 x 1024 partial sums */
#define S_BNQ    (S_BNP + 8192u)           /* 8 x 1024 partial sumsq */
#define S_TOTAL  (S_BNQ + 8192u)

__device__ float g_scratch[S_TOTAL];

// ============================================================================
// helpers
// ============================================================================
__device__ __forceinline__ uint32_t packh2(float lo, float hi) {
    uint32_t r; asm("cvt.rn.f16x2.f32 %0, %1, %2;" : "=r"(r) : "f"(hi), "f"(lo)); return r;
}

// truncation split: hi = top 11 significand bits (exact in fp16),
// lo = (v - hi) * 2048 (exact fp32 sub; fp16 keeps top 11 of remainder).
__device__ __forceinline__ void split11(float v, float& hi, float& lo) {
    hi = __uint_as_float(__float_as_uint(v) & 0xFFFFE000u);
    lo = __fmul_rn(__fsub_rn(v, hi), 2048.0f);
}

__device__ __forceinline__ float bnl(float x, float s, float h) {
    float o = fmaf(x, s, h);
    return o > 0.f ? o : 0.01f * o;
}

#define MMA_F16(acc, af, bf) asm volatile( \
    "mma.sync.aligned.m16n8k16.row.col.f32.f16.f16.f32 " \
    "{%0,%1,%2,%3}, {%4,%5,%6,%7}, {%8,%9}, {%0,%1,%2,%3};" \
    : "+f"((acc)[0]), "+f"((acc)[1]), "+f"((acc)[2]), "+f"((acc)[3]) \
    : "r"((af)[0]), "r"((af)[1]), "r"((af)[2]), "r"((af)[3]), \
      "r"((bf)[0]), "r"((bf)[1]))

#define PSTRIDE 20
#define PLANE   (128 * PSTRIDE)
#define BUFU32  (4 * PLANE)                /* 10240 u32 per buffer */
#define MMA_SMEM (2 * BUFU32 * 4 + 8192)   /* buffers + scale/shift = 90112 B */
#define LOGITS_SMEM (16 * PLANE * 4 + 4096)

// ============================================================================
// FP16-split tensor GEMM via mma.sync m16n8k16, tile 128x128, BK=32.
//   optional fused BN+LeakyReLU on A columns: scale/shift finalized IN-KERNEL
//   from partial stats (ps/pss, 8 parts) + gamma/beta into smem tables.
//   nsplit>1 -> partials at C + z*splitStride; nsplit==1 -> direct (+bias/relu)
// ============================================================================
__global__ __launch_bounds__(256, 1) void gemm_mma(const float* __restrict__ A,
        const float* __restrict__ B, const float* __restrict__ bias,
        float* __restrict__ C, int ldA, int ldc, int tchunks, int nsplit,
        size_t splitStride, const float* __restrict__ ps,
        const float* __restrict__ pss, const float* __restrict__ gw,
        const float* __restrict__ bw, int act) {
    extern __shared__ float smf[];
    uint32_t* smu = (uint32_t*)smf;
    float* sscale = smf + 20480;
    float* sshift = smf + 20480 + 1024;
    const int tid  = threadIdx.x;
    const int lane = tid & 31;
    const int g    = lane >> 2;
    const int t    = lane & 3;
    const int warp = tid >> 5;
    const int m0w  = (warp >> 2) * 64;
    const int n0w  = (warp & 3) * 32;
    const int n0   = blockIdx.x * 128;
    const int m0   = blockIdx.y * 128;

    const bool hasBN = (ps != nullptr);
    if (hasBN) {
        for (int f = tid; f < ldA; f += 256) {
            float s = 0.f, ss2 = 0.f;
            #pragma unroll
            for (int p = 0; p < 8; p++) { s += ps[p*ldA+f]; ss2 += pss[p*ldA+f]; }
            float mean = s * (1.0f / BATCH);
            float var = ss2 * (1.0f / BATCH) - mean * mean;
            float sc = rsqrtf(var + 1e-5f) * gw[f];
            sscale[f] = sc;
            sshift[f] = bw[f] - mean * sc;
        }
        __syncthreads();
    }

    const int cs = (int)(((long long)blockIdx.z * tchunks) / nsplit);
    const int ce = (int)(((long long)(blockIdx.z + 1) * tchunks) / nsplit);
    const int nchunks = ce - cs;
    const int kbase = cs * 32;

    const int rb = tid >> 3;
    const int q  = tid & 7;

    float accH[4][4][4], accL[4][4][4];
    #pragma unroll
    for (int mt = 0; mt < 4; mt++)
        #pragma unroll
        for (int nt = 0; nt < 4; nt++)
            #pragma unroll
            for (int i = 0; i < 4; i++) { accH[mt][nt][i] = 0.f; accL[mt][nt][i] = 0.f; }

    float4 stA[4], stB[4];

    {
        int f = kbase + q*4;
        float4 sc4, sh4;
        if (hasBN) { sc4 = *(float4*)&sscale[f]; sh4 = *(float4*)&sshift[f]; }
        #pragma unroll
        for (int j = 0; j < 4; j++) {
            stA[j] = *(const float4*)&A[(size_t)(m0 + rb + 32*j) * ldA + f];
            if (hasBN) {
                stA[j].x = bnl(stA[j].x, sc4.x, sh4.x);
                stA[j].y = bnl(stA[j].y, sc4.y, sh4.y);
                stA[j].z = bnl(stA[j].z, sc4.z, sh4.z);
                stA[j].w = bnl(stA[j].w, sc4.w, sh4.w);
            }
            stB[j] = *(const float4*)&B[(size_t)(n0 + rb + 32*j) * ldA + f];
        }
    }
    {
        uint32_t* ahi = smu;           uint32_t* alo = smu + PLANE;
        uint32_t* bhi = smu + 2*PLANE; uint32_t* blo = smu + 3*PLANE;
        #pragma unroll
        for (int j = 0; j < 4; j++) {
            int off = (rb + 32*j) * PSTRIDE + 2*q;
            float4 v = stA[j];
            float hx,lx,hy,ly,hz,lz,hw,lw;
            split11(v.x,hx,lx); split11(v.y,hy,ly); split11(v.z,hz,lz); split11(v.w,hw,lw);
            *(uint2*)&ahi[off] = make_uint2(packh2(hx,hy), packh2(hz,hw));
            *(uint2*)&alo[off] = make_uint2(packh2(lx,ly), packh2(lz,lw));
            v = stB[j];
            split11(v.x,hx,lx); split11(v.y,hy,ly); split11(v.z,hz,lz); split11(v.w,hw,lw);
            *(uint2*)&bhi[off] = make_uint2(packh2(hx,hy), packh2(hz,hw));
            *(uint2*)&blo[off] = make_uint2(packh2(lx,ly), packh2(lz,lw));
        }
    }
    __syncthreads();

    for (int c = 0; c < nchunks; c++) {
        if (c + 1 < nchunks) {
            int kp = kbase + (c + 1) * 32 + q*4;
            float4 sc4, sh4;
            if (hasBN) { sc4 = *(float4*)&sscale[kp]; sh4 = *(float4*)&sshift[kp]; }
            #pragma unroll
            for (int j = 0; j < 4; j++) {
                stA[j] = *(const float4*)&A[(size_t)(m0 + rb + 32*j) * ldA + kp];
                if (hasBN) {
                    stA[j].x = bnl(stA[j].x, sc4.x, sh4.x);
                    stA[j].y = bnl(stA[j].y, sc4.y, sh4.y);
                    stA[j].z = bnl(stA[j].z, sc4.z, sh4.z);
                    stA[j].w = bnl(stA[j].w, sc4.w, sh4.w);
                }
                stB[j] = *(const float4*)&B[(size_t)(n0 + rb + 32*j) * ldA + kp];
            }
        }

        const uint32_t* base = smu + (c & 1) * BUFU32;
        const uint32_t* pAhi = base;
        const uint32_t* pAlo = base + PLANE;
        const uint32_t* pBhi = base + 2*PLANE;
        const uint32_t* pBlo = base + 3*PLANE;

        #pragma unroll
        for (int ks = 0; ks < 2; ks++) {
            const int kk = ks * 8;
            uint32_t aH[4][4], aL[4][4], bH[4][2], bL[4][2];
            #pragma unroll
            for (int mt = 0; mt < 4; mt++) {
                int ro = (m0w + mt*16 + g) * PSTRIDE + kk + t;
                aH[mt][0] = pAhi[ro];
                aH[mt][1] = pAhi[ro + 8*PSTRIDE];
                aH[mt][2] = pAhi[ro + 4];
                aH[mt][3] = pAhi[ro + 8*PSTRIDE + 4];
                aL[mt][0] = pAlo[ro];
                aL[mt][1] = pAlo[ro + 8*PSTRIDE];
                aL[mt][2] = pAlo[ro + 4];
                aL[mt][3] = pAlo[ro + 8*PSTRIDE + 4];
            }
            #pragma unroll
            for (int nt = 0; nt < 4; nt++) {
                int rn = (n0w + nt*8 + g) * PSTRIDE + kk + t;
                bH[nt][0] = pBhi[rn];
                bH[nt][1] = pBhi[rn + 4];
                bL[nt][0] = pBlo[rn];
                bL[nt][1] = pBlo[rn + 4];
            }
            #pragma unroll
            for (int mt = 0; mt < 4; mt++)
                #pragma unroll
                for (int nt = 0; nt < 4; nt++) {
                    MMA_F16(accH[mt][nt], aH[mt], bH[nt]);
                    MMA_F16(accL[mt][nt], aH[mt], bL[nt]);
                    MMA_F16(accL[mt][nt], aL[mt], bH[nt]);
                }
        }

        if (c + 1 < nchunks) {
            uint32_t* bb = smu + ((c + 1) & 1) * BUFU32;
            uint32_t* ahi = bb;           uint32_t* alo = bb + PLANE;
            uint32_t* bhi = bb + 2*PLANE; uint32_t* blo = bb + 3*PLANE;
            #pragma unroll
            for (int j = 0; j < 4; j++) {
                int off = (rb + 32*j) * PSTRIDE + 2*q;
                float4 v = stA[j];
                float hx,lx,hy,ly,hz,lz,hw,lw;
                split11(v.x,hx,lx); split11(v.y,hy,ly); split11(v.z,hz,lz); split11(v.w,hw,lw);
                *(uint2*)&ahi[off] = make_uint2(packh2(hx,hy), packh2(hz,hw));
                *(uint2*)&alo[off] = make_uint2(packh2(lx,ly), packh2(lz,lw));
                v = stB[j];
                split11(v.x,hx,lx); split11(v.y,hy,ly); split11(v.z,hz,lz); split11(v.w,hw,lw);
                *(uint2*)&bhi[off] = make_uint2(packh2(hx,hy), packh2(hz,hw));
                *(uint2*)&blo[off] = make_uint2(packh2(lx,ly), packh2(lz,lw));
            }
        }
        __syncthreads();
    }

    const float inv2048 = 1.0f / 2048.0f;
    float* Cp = C + (size_t)blockIdx.z * splitStride;
    #pragma unroll
    for (int mt = 0; mt < 4; mt++) {
        #pragma unroll
        for (int nt = 0; nt < 4; nt++) {
            int row = m0 + m0w + mt*16 + g;
            int col = n0 + n0w + nt*8 + 2*t;
            float o0 = accH[mt][nt][0] + accL[mt][nt][0]*inv2048;
            float o1 = accH[mt][nt][1] + accL[mt][nt][1]*inv2048;
            float o2 = accH[mt][nt][2] + accL[mt][nt][2]*inv2048;
            float o3 = accH[mt][nt][3] + accL[mt][nt][3]*inv2048;
            if (bias) {
                float bx = bias[col], by = bias[col+1];
                o0 += bx; o1 += by; o2 += bx; o3 += by;
            }
            if (act) {
                o0 = fmaxf(o0, 0.f); o1 = fmaxf(o1, 0.f);
                o2 = fmaxf(o2, 0.f); o3 = fmaxf(o3, 0.f);
            }
            *(float2*)&Cp[(size_t)row * ldc + col] = make_float2(o0, o1);
            *(float2*)&Cp[(size_t)(row + 8) * ldc + col] = make_float2(o2, o3);
        }
    }
}

// ============================================================================
// Persistent logits GEMM: A[32768,128] @ Wfc[512,128]^T + bias, fused argmax.
// grid (4, 32): each CTA owns 128 cols, converts B ONCE, loops 8 m-tiles.
// ============================================================================
__global__ __launch_bounds__(256, 1) void gemm_logits(const float* __restrict__ A,
        const float* __restrict__ B, const float* __restrict__ bias,
        float2* __restrict__ amax) {
    extern __shared__ float smf[];
    uint32_t* smu = (uint32_t*)smf;
    float2* sred = (float2*)(smf + 16 * PLANE);
    const int tid  = threadIdx.x;
    const int lane = tid & 31;
    const int g    = lane >> 2;
    const int t    = lane & 3;
    const int warp = tid >> 5;
    const int m0w  = (warp >> 2) * 64;
    const int n0w  = (warp & 3) * 32;
    const int n0   = blockIdx.x * 128;
    const int warp_n = warp & 3;
    const int rb = tid >> 3;
    const int q  = tid & 7;
    const float inv2048 = 1.0f / 2048.0f;

    #pragma unroll
    for (int c = 0; c < 4; c++) {
        uint32_t* bhi = smu + (8 + c*2) * PLANE;
        uint32_t* blo = smu + (9 + c*2) * PLANE;
        #pragma unroll
        for (int j = 0; j < 4; j++) {
            int row = rb + 32*j;
            float4 v = *(const float4*)&B[(size_t)(n0 + row) * GH + c*32 + q*4];
            float hx,lx,hy,ly,hz,lz,hw,lw;
            split11(v.x,hx,lx); split11(v.y,hy,ly); split11(v.z,hz,lz); split11(v.w,hw,lw);
            int off = row * PSTRIDE + 2*q;
            *(uint2*)&bhi[off] = make_uint2(packh2(hx,hy), packh2(hz,hw));
            *(uint2*)&blo[off] = make_uint2(packh2(lx,ly), packh2(lz,lw));
        }
    }
    __syncthreads();

    for (int mi = 0; mi < 8; mi++) {
        const int m0 = (blockIdx.y * 8 + mi) * 128;

        #pragma unroll
        for (int c = 0; c < 4; c++) {
            uint32_t* ahi = smu + (c*2) * PLANE;
            uint32_t* alo = smu + (c*2 + 1) * PLANE;
            #pragma unroll
            for (int j = 0; j < 4; j++) {
                int row = rb + 32*j;
                float4 v = *(const float4*)&A[(size_t)(m0 + row) * GH + c*32 + q*4];
                float hx,lx,hy,ly,hz,lz,hw,lw;
                split11(v.x,hx,lx); split11(v.y,hy,ly); split11(v.z,hz,lz); split11(v.w,hw,lw);
                int off = row * PSTRIDE + 2*q;
                *(uint2*)&ahi[off] = make_uint2(packh2(hx,hy), packh2(hz,hw));
                *(uint2*)&alo[off] = make_uint2(packh2(lx,ly), packh2(lz,lw));
            }
        }
        __syncthreads();

        float accH[4][4][4], accL[4][4][4];
        #pragma unroll
        for (int mt = 0; mt < 4; mt++)
            #pragma unroll
            for (int nt = 0; nt < 4; nt++)
                #pragma unroll
                for (int i = 0; i < 4; i++) { accH[mt][nt][i] = 0.f; accL[mt][nt][i] = 0.f; }

        #pragma unroll
        for (int c = 0; c < 4; c++) {
            const uint32_t* pAhi = smu + (c*2) * PLANE;
            const uint32_t* pAlo = smu + (c*2 + 1) * PLANE;
            const uint32_t* pBhi = smu + (8 + c*2) * PLANE;
            const uint32_t* pBlo = smu + (9 + c*2) * PLANE;
            #pragma unroll
            for (int ks = 0; ks < 2; ks++) {
                const int kk = ks * 8;
                uint32_t aH[4][4], aL[4][4], bH[4][2], bL[4][2];
                #pragma unroll
                for (int mt = 0; mt < 4; mt++) {
                    int ro = (m0w + mt*16 + g) * PSTRIDE + kk + t;
                    aH[mt][0] = pAhi[ro];
                    aH[mt][1] = pAhi[ro + 8*PSTRIDE];
                    aH[mt][2] = pAhi[ro + 4];
                    aH[mt][3] = pAhi[ro + 8*PSTRIDE + 4];
                    aL[mt][0] = pAlo[ro];
                    aL[mt][1] = pAlo[ro + 8*PSTRIDE];
                    aL[mt][2] = pAlo[ro + 4];
                    aL[mt][3] = pAlo[ro + 8*PSTRIDE + 4];
                }
                #pragma unroll
                for (int nt = 0; nt < 4; nt++) {
                    int rn = (n0w + nt*8 + g) * PSTRIDE + kk + t;
                    bH[nt][0] = pBhi[rn];
                    bH[nt][1] = pBhi[rn + 4];
                    bL[nt][0] = pBlo[rn];
                    bL[nt][1] = pBlo[rn + 4];
                }
                #pragma unroll
                for (int mt = 0; mt < 4; mt++)
                    #pragma unroll
                    for (int nt = 0; nt < 4; nt++) {
                        MMA_F16(accH[mt][nt], aH[mt], bH[nt]);
                        MMA_F16(accL[mt][nt], aH[mt], bL[nt]);
                        MMA_F16(accL[mt][nt], aL[mt], bH[nt]);
                    }
            }
        }

        #pragma unroll
        for (int half = 0; half < 2; half++) {
            #pragma unroll
            for (int mt = 0; mt < 4; mt++) {
                int rloc = m0w + mt*16 + g + half*8;
                float best = -1e30f; int bidx = 0;
                #pragma unroll
                for (int nt = 0; nt < 4; nt++) {
                    #pragma unroll
                    for (int e = 0; e < 2; e++) {
                        int col = n0 + n0w + nt*8 + 2*t + e;
                        float v = accH[mt][nt][half*2 + e] + accL[mt][nt][half*2 + e]*inv2048
                                  + bias[col];
                        if (v > best) { best = v; bidx = col; }
                    }
                }
                #pragma unroll
                for (int o = 1; o < 4; o <<= 1) {
                    float ov = __shfl_xor_sync(0xffffffffu, best, o);
                    int   oi = __shfl_xor_sync(0xffffffffu, bidx, o);
                    if (ov > best || (ov == best && oi < bidx)) { best = ov; bidx = oi; }
                }
                if (t == 0) sred[rloc * 4 + warp_n] = make_float2(best, __int_as_float(bidx));
            }
        }
        __syncthreads();
        if (tid < 128) {
            float best = -1e30f; int bidx = 0x7fffffff;
            #pragma unroll
            for (int wn = 0; wn < 4; wn++) {
                float2 e = sred[tid * 4 + wn];
                int ei = __float_as_int(e.y);
                if (e.x > best || (e.x == best && ei < bidx)) { best = e.x; bidx = ei; }
            }
            amax[(size_t)(m0 + tid) * 4 + blockIdx.x] = make_float2(best, __int_as_float(bidx));
        }
        __syncthreads();
    }
}

// generic deterministic split-K reduce + bias (+optional relu), element-parallel
__global__ __launch_bounds__(256) void reduce_gen(const float* __restrict__ ws,
        const float* __restrict__ bias, float* __restrict__ out,
        int nsplit, int strideElems, int nmask, int act) {
    int i = blockIdx.x * 256 + threadIdx.x;
    float s = 0.0f;
    for (int sp = 0; sp < nsplit; sp++) s += ws[(size_t)sp * strideElems + i];
    s += bias[i & nmask];
    if (act) s = fmaxf(s, 0.f);
    out[i] = s;
}

// BN partial stats over 32-row groups (finalize happens in consumer gemm_mma)
__global__ void bn_part(const float* __restrict__ h, float* __restrict__ ps,
                        float* __restrict__ pss, int N) {
    int f = blockIdx.x * 256 + threadIdx.x;
    int part = blockIdx.y;
    float s = 0.f, ss = 0.f;
    int b0 = part * 32;
    #pragma unroll 4
    for (int b = b0; b < b0 + 32; b++) {
        float v = h[(size_t)b * N + f];
        s += v; ss += v * v;
    }
    ps[part * N + f] = s;
    pss[part * N + f] = ss;
}

// ============================================================================
// fp32x2 helpers + small GEMMs
// ============================================================================
__device__ __forceinline__ void fma2(ull &d, ull a, ull b) {
    asm("fma.rn.f32x2 %0, %1, %2, %0;" : "+l"(d) : "l"(a), "l"(b));
}
__device__ __forceinline__ ull pk2(float x, float y) {
    ull d; asm("mov.b64 %0, {%1, %2};" : "=l"(d) : "f"(x), "f"(y)); return d;
}
__device__ __forceinline__ float2 unpk2(ull d) {
    float2 r; asm("mov.b64 {%0, %1}, %2;" : "=f"(r.x), "=f"(r.y) : "l"(d)); return r;
}

// xp projection: C[M,N] = A[M,K] @ W[N,K]^T + bias
__global__ __launch_bounds__(256) void gemm_kernel(const float* __restrict__ A,
        const float* __restrict__ W, const float* __restrict__ bias,
        float* __restrict__ C, int M, int N, int K) {
    __shared__ float As[16][68];
    __shared__ float Bs[16][68];
    const int tid = threadIdx.x;
    const int n0 = blockIdx.x * 64;
    const int m0 = blockIdx.y * 64;
    const int trow = tid >> 4;
    const int tcol = tid & 15;
    const int lm = tid >> 2;
    const int lk = (tid & 3) * 4;

    ull acc[4][2];
    #pragma unroll
    for (int r = 0; r < 4; r++) { acc[r][0] = 0ull; acc[r][1] = 0ull; }

    for (int kk = 0; kk < K; kk += 16) {
        float4 va = *(const float4*)&A[(size_t)(m0 + lm) * K + kk + lk];
        float4 vb = *(const float4*)&W[(size_t)(n0 + lm) * K + kk + lk];
        As[lk+0][lm] = va.x; As[lk+1][lm] = va.y; As[lk+2][lm] = va.z; As[lk+3][lm] = va.w;
        Bs[lk+0][lm] = vb.x; Bs[lk+1][lm] = vb.y; Bs[lk+2][lm] = vb.z; Bs[lk+3][lm] = vb.w;
        __syncthreads();
        #pragma unroll
        for (int k = 0; k < 16; k++) {
            float4 a = *(const float4*)&As[k][trow * 4];
            const ull* bp = (const ull*)&Bs[k][tcol * 4];
            ull b0 = bp[0], b1 = bp[1];
            ull a0 = pk2(a.x, a.x), a1 = pk2(a.y, a.y);
            ull a2 = pk2(a.z, a.z), a3 = pk2(a.w, a.w);
            fma2(acc[0][0], a0, b0); fma2(acc[0][1], a0, b1);
            fma2(acc[1][0], a1, b0); fma2(acc[1][1], a1, b1);
            fma2(acc[2][0], a2, b0); fma2(acc[2][1], a2, b1);
            fma2(acc[3][0], a3, b0); fma2(acc[3][1], a3, b1);
        }
        __syncthreads();
    }

    #pragma unroll
    for (int r = 0; r < 4; r++) {
        int m = m0 + trow * 4 + r;
        int n = n0 + tcol * 4;
        float2 v0 = unpk2(acc[r][0]);
        float2 v1 = unpk2(acc[r][1]);
        *(float4*)&C[(size_t)m * N + n] = make_float4(v0.x + bias[n+0], v0.y + bias[n+1],
                                                      v1.x + bias[n+2], v1.y + bias[n+3]);
    }
}

// mu & lv in one CTA + fused reparameterization + output writes
__global__ __launch_bounds__(256) void gemm_mulv(const float* __restrict__ A,
        const float* __restrict__ Wmu, const float* __restrict__ bmu,
        const float* __restrict__ Wlv, const float* __restrict__ blv,
        const float* __restrict__ eps, float* __restrict__ z,
        float* __restrict__ out) {
    __shared__ float As[16][68];
    __shared__ float Bm[16][68];
    __shared__ float Bl[16][68];
    const int tid = threadIdx.x;
    const int n0 = blockIdx.x * 64;
    const int m0 = blockIdx.y * 64;
    const int trow = tid >> 4;
    const int tcol = tid & 15;
    const int lm = tid >> 2;
    const int lk = (tid & 3) * 4;

    ull am[4][2], al[4][2];
    #pragma unroll
    for (int r = 0; r < 4; r++) { am[r][0]=0ull; am[r][1]=0ull; al[r][0]=0ull; al[r][1]=0ull; }

    for (int kk = 0; kk < GH; kk += 16) {
        float4 va = *(const float4*)&A[(size_t)(m0 + lm) * GH + kk + lk];
        float4 vm = *(const float4*)&Wmu[(size_t)(n0 + lm) * GH + kk + lk];
        float4 vl = *(const float4*)&Wlv[(size_t)(n0 + lm) * GH + kk + lk];
        As[lk+0][lm] = va.x; As[lk+1][lm] = va.y; As[lk+2][lm] = va.z; As[lk+3][lm] = va.w;
        Bm[lk+0][lm] = vm.x; Bm[lk+1][lm] = vm.y; Bm[lk+2][lm] = vm.z; Bm[lk+3][lm] = vm.w;
        Bl[lk+0][lm] = vl.x; Bl[lk+1][lm] = vl.y; Bl[lk+2][lm] = vl.z; Bl[lk+3][lm] = vl.w;
        __syncthreads();
        #pragma unroll
        for (int k = 0; k < 16; k++) {
            float4 a = *(const float4*)&As[k][trow * 4];
            const ull* bmp = (const ull*)&Bm[k][tcol * 4];
            const ull* blp = (const ull*)&Bl[k][tcol * 4];
            ull bm0 = bmp[0], bm1 = bmp[1], bl0 = blp[0], bl1 = blp[1];
            ull a0 = pk2(a.x, a.x), a1 = pk2(a.y, a.y);
            ull a2 = pk2(a.z, a.z), a3 = pk2(a.w, a.w);
            fma2(am[0][0], a0, bm0); fma2(am[0][1], a0, bm1);
            fma2(am[1][0], a1, bm0); fma2(am[1][1], a1, bm1);
            fma2(am[2][0], a2, bm0); fma2(am[2][1], a2, bm1);
            fma2(am[3][0], a3, bm0); fma2(am[3][1], a3, bm1);
            fma2(al[0][0], a0, bl0); fma2(al[0][1], a0, bl1);
            fma2(al[1][0], a1, bl0); fma2(al[1][1], a1, bl1);
            fma2(al[2][0], a2, bl0); fma2(al[2][1], a2, bl1);
            fma2(al[3][0], a3, bl0); fma2(al[3][1], a3, bl1);
        }
        __syncthreads();
    }

    #pragma unroll
    for (int r = 0; r < 4; r++) {
        int m = m0 + trow * 4 + r;
        int n = n0 + tcol * 4;
        size_t idx = (size_t)m * GH + n;
        float2 m0v = unpk2(am[r][0]);
        float2 m1v = unpk2(am[r][1]);
        float2 l0v = unpk2(al[r][0]);
        float2 l1v = unpk2(al[r][1]);
        float mu0 = m0v.x + bmu[n+0], mu1 = m0v.y + bmu[n+1];
        float mu2 = m1v.x + bmu[n+2], mu3 = m1v.y + bmu[n+3];
        float lv0 = l0v.x + blv[n+0], lv1 = l0v.y + blv[n+1];
        float lv2 = l1v.x + blv[n+2], lv3 = l1v.y + blv[n+3];
        float4 ev = *(const float4*)&eps[idx];
        *(float4*)&out[OFF_MU + idx] = make_float4(mu0, mu1, mu2, mu3);
        *(float4*)&out[OFF_LV + idx] = make_float4(lv0, lv1, lv2, lv3);
        *(float4*)&z[idx] = make_float4(mu0 + ev.x * expf(0.5f * lv0),
                                        mu1 + ev.y * expf(0.5f * lv1),
                                        mu2 + ev.z * expf(0.5f * lv2),
                                        mu3 + ev.w * expf(0.5f * lv3));
    }
}

// ============================================================================
// GRU recurrence: 128 CTAs x 384 thr, 2 rows/CTA, register weights + f32x2
// ============================================================================
__global__ __launch_bounds__(384, 1) void gru_kernel(const float* __restrict__ xp,
        const float* __restrict__ Whh, const float* __restrict__ bhh,
        float* __restrict__ h2all) {
    __shared__ __align__(16) float h_a[128];
    __shared__ __align__(16) float h_b[128];
    __shared__ float hp_s[768];
    __shared__ float xp_s[768];
    const int j = threadIdx.x;
    const int row0 = blockIdx.x * 2;

    ull w2[64];
    #pragma unroll
    for (int kq = 0; kq < 32; kq++) {
        float4 v = *(const float4*)&Whh[(size_t)j * GH + kq * 4];
        w2[2*kq+0] = pk2(v.x, v.y);
        w2[2*kq+1] = pk2(v.z, v.w);
    }
    const float bh = bhh[j];
    xp_s[j]       = xp[(size_t)row0 * 384 + j];
    xp_s[384 + j] = xp[(size_t)(row0 + 1) * 384 + j];
    if (j < 128) { h_a[j] = 0.0f; h_b[j] = 0.0f; }
    __syncthreads();

    for (int t = 0; t < SEQ; t++) {
        ull accA = 0ull, accB = 0ull;
        #pragma unroll
        for (int kq = 0; kq < 32; kq++) {
            ulonglong2 ha = *(const ulonglong2*)&h_a[kq * 4];
            ulonglong2 hb = *(const ulonglong2*)&h_b[kq * 4];
            fma2(accA, w2[2*kq+0], ha.x);
            fma2(accA, w2[2*kq+1], ha.y);
            fma2(accB, w2[2*kq+0], hb.x);
            fma2(accB, w2[2*kq+1], hb.y);
        }
        float2 pa = unpk2(accA);
        float2 pb = unpk2(accB);
        hp_s[j]       = pa.x + pa.y + bh;
        hp_s[384 + j] = pb.x + pb.y + bh;
        __syncthreads();
        if (j < 256) {
            int r = j >> 7, u = j & 127;
            const float* hp = hp_s + r * 384;
            const float* xq = xp_s + r * 384;
            float rg = 1.0f / (1.0f + expf(-(xq[u]       + hp[u])));
            float zg = 1.0f / (1.0f + expf(-(xq[128 + u] + hp[128 + u])));
            float nn = tanhf(xq[256 + u] + rg * hp[256 + u]);
            float hold = r ? h_b[u] : h_a[u];
            float hnew = (1.0f - zg) * nn + zg * hold;
            if (r) h_b[u] = hnew; else h_a[u] = hnew;
            h2all[((size_t)t * BATCH + row0 + r) * GH + u] = hnew;
        }
        __syncthreads();
    }
}

// ============================================================================
// final argmax reduce over 4 partials + one-hot write
// ============================================================================
__global__ __launch_bounds__(256) void argmax_final(const float2* __restrict__ amp,
                                                    float* __restrict__ out) {
    int row  = blockIdx.x * 8 + (threadIdx.x >> 5);
    int lane = threadIdx.x & 31;
    float best = -1e30f; int bi = 0x7fffffff;
    if (lane < 4) {
        float2 e = amp[(size_t)row * 4 + lane];
        best = e.x; bi = __float_as_int(e.y);
    }
    #pragma unroll
    for (int o = 1; o < 4; o <<= 1) {
        float ov = __shfl_xor_sync(0xffffffffu, best, o);
        int   oi = __shfl_xor_sync(0xffffffffu, bi, o);
        if (ov > best || (ov == best && oi < bi)) { best = ov; bi = oi; }
    }
    bi = __shfl_sync(0xffffffffu, bi, 0);
    int t = row >> 8, b = row & 255;
    float* op = out + (size_t)b * (SEQ * VOCAB) + (size_t)t * VOCAB;
    #pragma unroll
    for (int q = 0; q < 4; q++) {
        int c = lane * 16 + q * 4;
        *(float4*)&op[c] = make_float4(c == bi ? 1.f : 0.f, c + 1 == bi ? 1.f : 0.f,
                                       c + 2 == bi ? 1.f : 0.f, c + 3 == bi ? 1.f : 0.f);
    }
}

// ============================================================================
// launcher
// ============================================================================
extern "C" void kernel_launch(void* const* d_in, const int* in_sizes, int n_in,
                              void* d_out, int out_size) {
    (void)in_sizes; (void)n_in; (void)out_size;
    const float* x    = (const float*)d_in[0];
    const float* eps  = (const float*)d_in[1];
    const float* W0   = (const float*)d_in[2];
    const float* b0   = (const float*)d_in[3];
    const float* g0   = (const float*)d_in[4];
    const float* be0  = (const float*)d_in[5];
    const float* W1   = (const float*)d_in[6];
    const float* b1   = (const float*)d_in[7];
    const float* g1   = (const float*)d_in[8];
    const float* be1  = (const float*)d_in[9];
    const float* W2   = (const float*)d_in[10];
    const float* b2   = (const float*)d_in[11];
    const float* g2   = (const float*)d_in[12];
    const float* be2  = (const float*)d_in[13];
    const float* Wout = (const float*)d_in[14];
    const float* bout = (const float*)d_in[15];
    const float* Wmu  = (const float*)d_in[16];
    const float* bmu  = (const float*)d_in[17];
    const float* Wlv  = (const float*)d_in[18];
    const float* blv  = (const float*)d_in[19];
    const float* Wih  = (const float*)d_in[20];
    const float* bih  = (const float*)d_in[21];
    const float* Whh  = (const float*)d_in[22];
    const float* bhh  = (const float*)d_in[23];
    const float* Wfc  = (const float*)d_in[24];
    const float* bfc  = (const float*)d_in[25];
    float* out = (float*)d_out;

    float* S = nullptr;
    cudaGetSymbolAddress((void**)&S, g_scratch);

    cudaFuncSetAttribute(gemm_mma, cudaFuncAttributeMaxDynamicSharedMemorySize, MMA_SMEM);
    cudaFuncSetAttribute(gemm_logits, cudaFuncAttributeMaxDynamicSharedMemorySize, LOGITS_SMEM);

    // --- encoder layer 0: fp16-split mma, split-K=9 (144 CTAs = 1 wave) ---
    gemm_mma<<<dim3(8, 2, GSPLITS), 256, MMA_SMEM>>>(x, W0, nullptr, S + S_WS,
        K0, N0, TCHUNKS0, GSPLITS, (size_t)BATCH * N0,
        nullptr, nullptr, nullptr, nullptr, 0);
    reduce_gen<<<1024, 256>>>(S + S_WS, b0, S + S_H0, GSPLITS, BATCH * N0, N0 - 1, 0);
    bn_part<<<dim3(4, 8), 256>>>(S + S_H0, S + S_BNP, S + S_BNQ, 1024);

    // --- encoder layer 1: 1024 -> 512, split-K=16 (BN0+lrelu finalized in-kernel) ---
    gemm_mma<<<dim3(4, 2, 16), 256, MMA_SMEM>>>(S + S_H0, W1, nullptr, S + S_WS,
        1024, 512, 32, 16, (size_t)BATCH * 512,
        S + S_BNP, S + S_BNQ, g0, be0, 0);
    reduce_gen<<<512, 256>>>(S + S_WS, b1, S + S_H1, 16, BATCH * 512, 511, 0);
    bn_part<<<dim3(2, 8), 256>>>(S + S_H1, S + S_BNP, S + S_BNQ, 512);

    // --- encoder layer 2: 512 -> 256, split-K=8 (BN1 fused) ---
    gemm_mma<<<dim3(2, 2, 8), 256, MMA_SMEM>>>(S + S_H1, W2, nullptr, S + S_WS,
        512, 256, 16, 8, (size_t)BATCH * 256,
        S + S_BNP, S + S_BNQ, g1, be1, 0);
    reduce_gen<<<256, 256>>>(S + S_WS, b2, S + S_H2B, 8, BATCH * 256, 255, 0);
    bn_part<<<dim3(1, 8), 256>>>(S + S_H2B, S + S_BNP, S + S_BNQ, 256);

    // --- out layer: 256 -> 128, split-K=8 (BN2 fused), relu in reduce ---
    gemm_mma<<<dim3(1, 2, 8), 256, MMA_SMEM>>>(S + S_H2B, Wout, nullptr, S + S_WS,
        256, 128, 8, 8, (size_t)BATCH * 128,
        S + S_BNP, S + S_BNQ, g2, be2, 0);
    reduce_gen<<<128, 256>>>(S + S_WS, bout, S + S_HENC, 8, BATCH * 128, 127, 1);

    // --- mu & lv & reparameterize in ONE kernel (writes out mu/lv + z) ---
    gemm_mulv<<<dim3(2, 4), 256>>>(S + S_HENC, Wmu, bmu, Wlv, blv, eps, S + S_Z, out);

    // --- GRU input projection ---
    gemm_kernel<<<dim3(6, 4), 256>>>(S + S_Z, Wih, bih, S + S_XP, 256, 384, 128);

    // --- GRU recurrence ---
    gru_kernel<<<128, 384>>>(S + S_XP, Whh, bhh, S + S_H2ALL);

    // --- persistent logits GEMM with fused bias+argmax (1 wave) ---
    gemm_logits<<<dim3(4, 32), 256, LOGITS_SMEM>>>(S + S_H2ALL, Wfc, bfc,
                                                   (float2*)(S + S_AMP));
    argmax_final<<<4096, 256>>>((const float2*)(S + S_AMP), out);
}

// round 15
// speedup vs baseline: 1.0926x; 1.0035x over previous
#include <cuda_runtime.h>
#include <math.h>
#include <stdint.h>

typedef unsigned long long ull;

#define BATCH 256
#define SEQ   128
#define VOCAB 512
#define GH    128
#define K0    65536
#define N0    1024
#define GSPLITS 9
#define TCHUNKS0 2048          /* K0/32 */
#define NPARTS 16

#define OFF_MU (BATCH*SEQ*VOCAB)
#define OFF_LV (OFF_MU + BATCH*GH)

// ---- scratch layout (single static __device__ array) ----
#define S_WS     0u                        /* split-K partials */
#define S_H0     (S_WS + 2359296u)         /* 256x1024 (raw, pre-BN) */
#define S_H1     (S_H0 + 262144u)          /* 256x512  (raw) */
#define S_H2B    (S_H1 + 131072u)          /* 256x256  (raw) */
#define S_HENC   (S_H2B + 65536u)          /* 256x128  */
#define S_Z      (S_HENC + 32768u)
#define S_XP     (S_Z + 32768u)            /* 256x384  */
#define S_H2ALL  (S_XP + 98304u)           /* 32768x128 */
#define S_AMP    (S_H2ALL + 4194304u)      /* 32768x4 float2 */
#define S_BNP    (S_AMP + 262144u)         /* 16 x 1024 partial sums */
#define S_BNQ    (S_BNP + 16384u)          /* 16 x 1024 partial sumsq */
#define S_TOTAL  (S_BNQ + 16384u)

__device__ float g_scratch[S_TOTAL];

// ============================================================================
// helpers
// ============================================================================
__device__ __forceinline__ uint32_t packh2(float lo, float hi) {
    uint32_t r; asm("cvt.rn.f16x2.f32 %0, %1, %2;" : "=r"(r) : "f"(hi), "f"(lo)); return r;
}

// truncation split: hi = top 11 significand bits (exact in fp16),
// lo = (v - hi) * 2048 (exact fp32 sub; fp16 keeps top 11 of remainder).
__device__ __forceinline__ void split11(float v, float& hi, float& lo) {
    hi = __uint_as_float(__float_as_uint(v) & 0xFFFFE000u);
    lo = __fmul_rn(__fsub_rn(v, hi), 2048.0f);
}

__device__ __forceinline__ float bnl(float x, float s, float h) {
    float o = fmaf(x, s, h);
    return o > 0.f ? o : 0.01f * o;
}

#define MMA_F16(acc, af, bf) asm volatile( \
    "mma.sync.aligned.m16n8k16.row.col.f32.f16.f16.f32 " \
    "{%0,%1,%2,%3}, {%4,%5,%6,%7}, {%8,%9}, {%0,%1,%2,%3};" \
    : "+f"((acc)[0]), "+f"((acc)[1]), "+f"((acc)[2]), "+f"((acc)[3]) \
    : "r"((af)[0]), "r"((af)[1]), "r"((af)[2]), "r"((af)[3]), \
      "r"((bf)[0]), "r"((bf)[1]))

#define PSTRIDE 20
#define PLANE   (128 * PSTRIDE)
#define BUFU32  (4 * PLANE)                /* 10240 u32 per buffer */
#define MMA_SMEM (2 * BUFU32 * 4 + 8192)   /* buffers + scale/shift = 90112 B */
#define LOGITS_SMEM (16 * PLANE * 4 + 4096)

// ============================================================================
// FP16-split tensor GEMM via mma.sync m16n8k16, tile 128x128, BK=32.
//   optional fused BN+LeakyReLU on A columns: scale/shift for THIS CTA's
//   K-range finalized in-prologue from 16 partial stats + gamma/beta.
//   nsplit>1 -> partials at C + z*splitStride; nsplit==1 -> direct (+bias/relu)
// ============================================================================
__global__ __launch_bounds__(256, 1) void gemm_mma(const float* __restrict__ A,
        const float* __restrict__ B, const float* __restrict__ bias,
        float* __restrict__ C, int ldA, int ldc, int tchunks, int nsplit,
        size_t splitStride, const float* __restrict__ ps,
        const float* __restrict__ pss, const float* __restrict__ gw,
        const float* __restrict__ bw, int act) {
    extern __shared__ float smf[];
    uint32_t* smu = (uint32_t*)smf;
    float* sscale = smf + 20480;
    float* sshift = smf + 20480 + 1024;
    const int tid  = threadIdx.x;
    const int lane = tid & 31;
    const int g    = lane >> 2;
    const int t    = lane & 3;
    const int warp = tid >> 5;
    const int m0w  = (warp >> 2) * 64;
    const int n0w  = (warp & 3) * 32;
    const int n0   = blockIdx.x * 128;
    const int m0   = blockIdx.y * 128;

    const int cs = (int)(((long long)blockIdx.z * tchunks) / nsplit);
    const int ce = (int)(((long long)(blockIdx.z + 1) * tchunks) / nsplit);
    const int nchunks = ce - cs;
    const int kbase = cs * 32;
    const int kspan = nchunks * 32;

    const bool hasBN = (ps != nullptr);
    if (hasBN) {
        // finalize only the K-range this CTA touches
        for (int fo = tid; fo < kspan; fo += 256) {
            int f = kbase + fo;
            float s = 0.f, ss2 = 0.f;
            #pragma unroll
            for (int p = 0; p < NPARTS; p++) { s += ps[p*ldA+f]; ss2 += pss[p*ldA+f]; }
            float mean = s * (1.0f / BATCH);
            float var = ss2 * (1.0f / BATCH) - mean * mean;
            float sc = rsqrtf(var + 1e-5f) * gw[f];
            sscale[f] = sc;
            sshift[f] = bw[f] - mean * sc;
        }
        __syncthreads();
    }

    const int rb = tid >> 3;
    const int q  = tid & 7;

    float accH[4][4][4], accL[4][4][4];
    #pragma unroll
    for (int mt = 0; mt < 4; mt++)
        #pragma unroll
        for (int nt = 0; nt < 4; nt++)
            #pragma unroll
            for (int i = 0; i < 4; i++) { accH[mt][nt][i] = 0.f; accL[mt][nt][i] = 0.f; }

    float4 stA[4], stB[4];

    {
        int f = kbase + q*4;
        float4 sc4, sh4;
        if (hasBN) { sc4 = *(float4*)&sscale[f]; sh4 = *(float4*)&sshift[f]; }
        #pragma unroll
        for (int j = 0; j < 4; j++) {
            stA[j] = *(const float4*)&A[(size_t)(m0 + rb + 32*j) * ldA + f];
            if (hasBN) {
                stA[j].x = bnl(stA[j].x, sc4.x, sh4.x);
                stA[j].y = bnl(stA[j].y, sc4.y, sh4.y);
                stA[j].z = bnl(stA[j].z, sc4.z, sh4.z);
                stA[j].w = bnl(stA[j].w, sc4.w, sh4.w);
            }
            stB[j] = *(const float4*)&B[(size_t)(n0 + rb + 32*j) * ldA + f];
        }
    }
    {
        uint32_t* ahi = smu;           uint32_t* alo = smu + PLANE;
        uint32_t* bhi = smu + 2*PLANE; uint32_t* blo = smu + 3*PLANE;
        #pragma unroll
        for (int j = 0; j < 4; j++) {
            int off = (rb + 32*j) * PSTRIDE + 2*q;
            float4 v = stA[j];
            float hx,lx,hy,ly,hz,lz,hw,lw;
            split11(v.x,hx,lx); split11(v.y,hy,ly); split11(v.z,hz,lz); split11(v.w,hw,lw);
            *(uint2*)&ahi[off] = make_uint2(packh2(hx,hy), packh2(hz,hw));
            *(uint2*)&alo[off] = make_uint2(packh2(lx,ly), packh2(lz,lw));
            v = stB[j];
            split11(v.x,hx,lx); split11(v.y,hy,ly); split11(v.z,hz,lz); split11(v.w,hw,lw);
            *(uint2*)&bhi[off] = make_uint2(packh2(hx,hy), packh2(hz,hw));
            *(uint2*)&blo[off] = make_uint2(packh2(lx,ly), packh2(lz,lw));
        }
    }
    __syncthreads();

    for (int c = 0; c < nchunks; c++) {
        if (c + 1 < nchunks) {
            int kp = kbase + (c + 1) * 32 + q*4;
            float4 sc4, sh4;
            if (hasBN) { sc4 = *(float4*)&sscale[kp]; sh4 = *(float4*)&sshift[kp]; }
            #pragma unroll
            for (int j = 0; j < 4; j++) {
                stA[j] = *(const float4*)&A[(size_t)(m0 + rb + 32*j) * ldA + kp];
                if (hasBN) {
                    stA[j].x = bnl(stA[j].x, sc4.x, sh4.x);
                    stA[j].y = bnl(stA[j].y, sc4.y, sh4.y);
                    stA[j].z = bnl(stA[j].z, sc4.z, sh4.z);
                    stA[j].w = bnl(stA[j].w, sc4.w, sh4.w);
                }
                stB[j] = *(const float4*)&B[(size_t)(n0 + rb + 32*j) * ldA + kp];
            }
        }

        const uint32_t* base = smu + (c & 1) * BUFU32;
        const uint32_t* pAhi = base;
        const uint32_t* pAlo = base + PLANE;
        const uint32_t* pBhi = base + 2*PLANE;
        const uint32_t* pBlo = base + 3*PLANE;

        #pragma unroll
        for (int ks = 0; ks < 2; ks++) {
            const int kk = ks * 8;
            uint32_t aH[4][4], aL[4][4], bH[4][2], bL[4][2];
            #pragma unroll
            for (int mt = 0; mt < 4; mt++) {
                int ro = (m0w + mt*16 + g) * PSTRIDE + kk + t;
                aH[mt][0] = pAhi[ro];
                aH[mt][1] = pAhi[ro + 8*PSTRIDE];
                aH[mt][2] = pAhi[ro + 4];
                aH[mt][3] = pAhi[ro + 8*PSTRIDE + 4];
                aL[mt][0] = pAlo[ro];
                aL[mt][1] = pAlo[ro + 8*PSTRIDE];
                aL[mt][2] = pAlo[ro + 4];
                aL[mt][3] = pAlo[ro + 8*PSTRIDE + 4];
            }
            #pragma unroll
            for (int nt = 0; nt < 4; nt++) {
                int rn = (n0w + nt*8 + g) * PSTRIDE + kk + t;
                bH[nt][0] = pBhi[rn];
                bH[nt][1] = pBhi[rn + 4];
                bL[nt][0] = pBlo[rn];
                bL[nt][1] = pBlo[rn + 4];
            }
            #pragma unroll
            for (int mt = 0; mt < 4; mt++)
                #pragma unroll
                for (int nt = 0; nt < 4; nt++) {
                    MMA_F16(accH[mt][nt], aH[mt], bH[nt]);
                    MMA_F16(accL[mt][nt], aH[mt], bL[nt]);
                    MMA_F16(accL[mt][nt], aL[mt], bH[nt]);
                }
        }

        if (c + 1 < nchunks) {
            uint32_t* bb = smu + ((c + 1) & 1) * BUFU32;
            uint32_t* ahi = bb;           uint32_t* alo = bb + PLANE;
            uint32_t* bhi = bb + 2*PLANE; uint32_t* blo = bb + 3*PLANE;
            #pragma unroll
            for (int j = 0; j < 4; j++) {
                int off = (rb + 32*j) * PSTRIDE + 2*q;
                float4 v = stA[j];
                float hx,lx,hy,ly,hz,lz,hw,lw;
                split11(v.x,hx,lx); split11(v.y,hy,ly); split11(v.z,hz,lz); split11(v.w,hw,lw);
                *(uint2*)&ahi[off] = make_uint2(packh2(hx,hy), packh2(hz,hw));
                *(uint2*)&alo[off] = make_uint2(packh2(lx,ly), packh2(lz,lw));
                v = stB[j];
                split11(v.x,hx,lx); split11(v.y,hy,ly); split11(v.z,hz,lz); split11(v.w,hw,lw);
                *(uint2*)&bhi[off] = make_uint2(packh2(hx,hy), packh2(hz,hw));
                *(uint2*)&blo[off] = make_uint2(packh2(lx,ly), packh2(lz,lw));
            }
        }
        __syncthreads();
    }

    const float inv2048 = 1.0f / 2048.0f;
    float* Cp = C + (size_t)blockIdx.z * splitStride;
    #pragma unroll
    for (int mt = 0; mt < 4; mt++) {
        #pragma unroll
        for (int nt = 0; nt < 4; nt++) {
            int row = m0 + m0w + mt*16 + g;
            int col = n0 + n0w + nt*8 + 2*t;
            float o0 = accH[mt][nt][0] + accL[mt][nt][0]*inv2048;
            float o1 = accH[mt][nt][1] + accL[mt][nt][1]*inv2048;
            float o2 = accH[mt][nt][2] + accL[mt][nt][2]*inv2048;
            float o3 = accH[mt][nt][3] + accL[mt][nt][3]*inv2048;
            if (bias) {
                float bx = bias[col], by = bias[col+1];
                o0 += bx; o1 += by; o2 += bx; o3 += by;
            }
            if (act) {
                o0 = fmaxf(o0, 0.f); o1 = fmaxf(o1, 0.f);
                o2 = fmaxf(o2, 0.f); o3 = fmaxf(o3, 0.f);
            }
            *(float2*)&Cp[(size_t)row * ldc + col] = make_float2(o0, o1);
            *(float2*)&Cp[(size_t)(row + 8) * ldc + col] = make_float2(o2, o3);
        }
    }
}

// ============================================================================
// Persistent logits GEMM: A[32768,128] @ Wfc[512,128]^T + bias, fused argmax.
// grid (4, 32): each CTA owns 128 cols, converts B ONCE, loops 8 m-tiles.
// ============================================================================
__global__ __launch_bounds__(256, 1) void gemm_logits(const float* __restrict__ A,
        const float* __restrict__ B, const float* __restrict__ bias,
        float2* __restrict__ amax) {
    extern __shared__ float smf[];
    uint32_t* smu = (uint32_t*)smf;
    float2* sred = (float2*)(smf + 16 * PLANE);
    const int tid  = threadIdx.x;
    const int lane = tid & 31;
    const int g    = lane >> 2;
    const int t    = lane & 3;
    const int warp = tid >> 5;
    const int m0w  = (warp >> 2) * 64;
    const int n0w  = (warp & 3) * 32;
    const int n0   = blockIdx.x * 128;
    const int warp_n = warp & 3;
    const int rb = tid >> 3;
    const int q  = tid & 7;
    const float inv2048 = 1.0f / 2048.0f;

    #pragma unroll
    for (int c = 0; c < 4; c++) {
        uint32_t* bhi = smu + (8 + c*2) * PLANE;
        uint32_t* blo = smu + (9 + c*2) * PLANE;
        #pragma unroll
        for (int j = 0; j < 4; j++) {
            int row = rb + 32*j;
            float4 v = *(const float4*)&B[(size_t)(n0 + row) * GH + c*32 + q*4];
            float hx,lx,hy,ly,hz,lz,hw,lw;
            split11(v.x,hx,lx); split11(v.y,hy,ly); split11(v.z,hz,lz); split11(v.w,hw,lw);
            int off = row * PSTRIDE + 2*q;
            *(uint2*)&bhi[off] = make_uint2(packh2(hx,hy), packh2(hz,hw));
            *(uint2*)&blo[off] = make_uint2(packh2(lx,ly), packh2(lz,lw));
        }
    }
    __syncthreads();

    for (int mi = 0; mi < 8; mi++) {
        const int m0 = (blockIdx.y * 8 + mi) * 128;

        #pragma unroll
        for (int c = 0; c < 4; c++) {
            uint32_t* ahi = smu + (c*2) * PLANE;
            uint32_t* alo = smu + (c*2 + 1) * PLANE;
            #pragma unroll
            for (int j = 0; j < 4; j++) {
                int row = rb + 32*j;
                float4 v = *(const float4*)&A[(size_t)(m0 + row) * GH + c*32 + q*4];
                float hx,lx,hy,ly,hz,lz,hw,lw;
                split11(v.x,hx,lx); split11(v.y,hy,ly); split11(v.z,hz,lz); split11(v.w,hw,lw);
                int off = row * PSTRIDE + 2*q;
                *(uint2*)&ahi[off] = make_uint2(packh2(hx,hy), packh2(hz,hw));
                *(uint2*)&alo[off] = make_uint2(packh2(lx,ly), packh2(lz,lw));
            }
        }
        __syncthreads();

        float accH[4][4][4], accL[4][4][4];
        #pragma unroll
        for (int mt = 0; mt < 4; mt++)
            #pragma unroll
            for (int nt = 0; nt < 4; nt++)
                #pragma unroll
                for (int i = 0; i < 4; i++) { accH[mt][nt][i] = 0.f; accL[mt][nt][i] = 0.f; }

        #pragma unroll
        for (int c = 0; c < 4; c++) {
            const uint32_t* pAhi = smu + (c*2) * PLANE;
            const uint32_t* pAlo = smu + (c*2 + 1) * PLANE;
            const uint32_t* pBhi = smu + (8 + c*2) * PLANE;
            const uint32_t* pBlo = smu + (9 + c*2) * PLANE;
            #pragma unroll
            for (int ks = 0; ks < 2; ks++) {
                const int kk = ks * 8;
                uint32_t aH[4][4], aL[4][4], bH[4][2], bL[4][2];
                #pragma unroll
                for (int mt = 0; mt < 4; mt++) {
                    int ro = (m0w + mt*16 + g) * PSTRIDE + kk + t;
                    aH[mt][0] = pAhi[ro];
                    aH[mt][1] = pAhi[ro + 8*PSTRIDE];
                    aH[mt][2] = pAhi[ro + 4];
                    aH[mt][3] = pAhi[ro + 8*PSTRIDE + 4];
                    aL[mt][0] = pAlo[ro];
                    aL[mt][1] = pAlo[ro + 8*PSTRIDE];
                    aL[mt][2] = pAlo[ro + 4];
                    aL[mt][3] = pAlo[ro + 8*PSTRIDE + 4];
                }
                #pragma unroll
                for (int nt = 0; nt < 4; nt++) {
                    int rn = (n0w + nt*8 + g) * PSTRIDE + kk + t;
                    bH[nt][0] = pBhi[rn];
                    bH[nt][1] = pBhi[rn + 4];
                    bL[nt][0] = pBlo[rn];
                    bL[nt][1] = pBlo[rn + 4];
                }
                #pragma unroll
                for (int mt = 0; mt < 4; mt++)
                    #pragma unroll
                    for (int nt = 0; nt < 4; nt++) {
                        MMA_F16(accH[mt][nt], aH[mt], bH[nt]);
                        MMA_F16(accL[mt][nt], aH[mt], bL[nt]);
                        MMA_F16(accL[mt][nt], aL[mt], bH[nt]);
                    }
            }
        }

        #pragma unroll
        for (int half = 0; half < 2; half++) {
            #pragma unroll
            for (int mt = 0; mt < 4; mt++) {
                int rloc = m0w + mt*16 + g + half*8;
                float best = -1e30f; int bidx = 0;
                #pragma unroll
                for (int nt = 0; nt < 4; nt++) {
                    #pragma unroll
                    for (int e = 0; e < 2; e++) {
                        int col = n0 + n0w + nt*8 + 2*t + e;
                        float v = accH[mt][nt][half*2 + e] + accL[mt][nt][half*2 + e]*inv2048
                                  + bias[col];
                        if (v > best) { best = v; bidx = col; }
                    }
                }
                #pragma unroll
                for (int o = 1; o < 4; o <<= 1) {
                    float ov = __shfl_xor_sync(0xffffffffu, best, o);
                    int   oi = __shfl_xor_sync(0xffffffffu, bidx, o);
                    if (ov > best || (ov == best && oi < bidx)) { best = ov; bidx = oi; }
                }
                if (t == 0) sred[rloc * 4 + warp_n] = make_float2(best, __int_as_float(bidx));
            }
        }
        __syncthreads();
        if (tid < 128) {
            float best = -1e30f; int bidx = 0x7fffffff;
            #pragma unroll
            for (int wn = 0; wn < 4; wn++) {
                float2 e = sred[tid * 4 + wn];
                int ei = __float_as_int(e.y);
                if (e.x > best || (e.x == best && ei < bidx)) { best = e.x; bidx = ei; }
            }
            amax[(size_t)(m0 + tid) * 4 + blockIdx.x] = make_float2(best, __int_as_float(bidx));
        }
        __syncthreads();
    }
}

// vectorized deterministic split-K reduce + bias (+optional relu)
// processes 4 elements per thread; totalElems must be /1024
__global__ __launch_bounds__(256) void reduce_gen(const float* __restrict__ ws,
        const float* __restrict__ bias, float* __restrict__ out,
        int nsplit, int strideElems, int nmask, int act) {
    int i4 = (blockIdx.x * 256 + threadIdx.x) * 4;
    float4 s = make_float4(0.f, 0.f, 0.f, 0.f);
    for (int sp = 0; sp < nsplit; sp++) {
        float4 v = *(const float4*)&ws[(size_t)sp * strideElems + i4];
        s.x += v.x; s.y += v.y; s.z += v.z; s.w += v.w;
    }
    int f = i4 & nmask;
    float4 b = *(const float4*)&bias[f];
    s.x += b.x; s.y += b.y; s.z += b.z; s.w += b.w;
    if (act) {
        s.x = fmaxf(s.x, 0.f); s.y = fmaxf(s.y, 0.f);
        s.z = fmaxf(s.z, 0.f); s.w = fmaxf(s.w, 0.f);
    }
    *(float4*)&out[i4] = s;
}

// BN partial stats over 16-row groups (finalize happens in consumer gemm_mma)
__global__ void bn_part(const float* __restrict__ h, float* __restrict__ ps,
                        float* __restrict__ pss, int N) {
    int f = blockIdx.x * 256 + threadIdx.x;
    int part = blockIdx.y;
    float s = 0.f, ss = 0.f;
    int b0 = part * 16;
    #pragma unroll 4
    for (int b = b0; b < b0 + 16; b++) {
        float v = h[(size_t)b * N + f];
        s += v; ss += v * v;
    }
    ps[part * N + f] = s;
    pss[part * N + f] = ss;
}

// ============================================================================
// fp32x2 helpers + small GEMMs
// ============================================================================
__device__ __forceinline__ void fma2(ull &d, ull a, ull b) {
    asm("fma.rn.f32x2 %0, %1, %2, %0;" : "+l"(d) : "l"(a), "l"(b));
}
__device__ __forceinline__ ull pk2(float x, float y) {
    ull d; asm("mov.b64 %0, {%1, %2};" : "=l"(d) : "f"(x), "f"(y)); return d;
}
__device__ __forceinline__ float2 unpk2(ull d) {
    float2 r; asm("mov.b64 {%0, %1}, %2;" : "=f"(r.x), "=f"(r.y) : "l"(d)); return r;
}

// xp projection: C[M,N] = A[M,K] @ W[N,K]^T + bias
__global__ __launch_bounds__(256) void gemm_kernel(const float* __restrict__ A,
        const float* __restrict__ W, const float* __restrict__ bias,
        float* __restrict__ C, int M, int N, int K) {
    __shared__ float As[16][68];
    __shared__ float Bs[16][68];
    const int tid = threadIdx.x;
    const int n0 = blockIdx.x * 64;
    const int m0 = blockIdx.y * 64;
    const int trow = tid >> 4;
    const int tcol = tid & 15;
    const int lm = tid >> 2;
    const int lk = (tid & 3) * 4;

    ull acc[4][2];
    #pragma unroll
    for (int r = 0; r < 4; r++) { acc[r][0] = 0ull; acc[r][1] = 0ull; }

    for (int kk = 0; kk < K; kk += 16) {
        float4 va = *(const float4*)&A[(size_t)(m0 + lm) * K + kk + lk];
        float4 vb = *(const float4*)&W[(size_t)(n0 + lm) * K + kk + lk];
        As[lk+0][lm] = va.x; As[lk+1][lm] = va.y; As[lk+2][lm] = va.z; As[lk+3][lm] = va.w;
        Bs[lk+0][lm] = vb.x; Bs[lk+1][lm] = vb.y; Bs[lk+2][lm] = vb.z; Bs[lk+3][lm] = vb.w;
        __syncthreads();
        #pragma unroll
        for (int k = 0; k < 16; k++) {
            float4 a = *(const float4*)&As[k][trow * 4];
            const ull* bp = (const ull*)&Bs[k][tcol * 4];
            ull b0 = bp[0], b1 = bp[1];
            ull a0 = pk2(a.x, a.x), a1 = pk2(a.y, a.y);
            ull a2 = pk2(a.z, a.z), a3 = pk2(a.w, a.w);
            fma2(acc[0][0], a0, b0); fma2(acc[0][1], a0, b1);
            fma2(acc[1][0], a1, b0); fma2(acc[1][1], a1, b1);
            fma2(acc[2][0], a2, b0); fma2(acc[2][1], a2, b1);
            fma2(acc[3][0], a3, b0); fma2(acc[3][1], a3, b1);
        }
        __syncthreads();
    }

    #pragma unroll
    for (int r = 0; r < 4; r++) {
        int m = m0 + trow * 4 + r;
        int n = n0 + tcol * 4;
        float2 v0 = unpk2(acc[r][0]);
        float2 v1 = unpk2(acc[r][1]);
        *(float4*)&C[(size_t)m * N + n] = make_float4(v0.x + bias[n+0], v0.y + bias[n+1],
                                                      v1.x + bias[n+2], v1.y + bias[n+3]);
    }
}

// mu & lv in one CTA + fused reparameterization + output writes
__global__ __launch_bounds__(256) void gemm_mulv(const float* __restrict__ A,
        const float* __restrict__ Wmu, const float* __restrict__ bmu,
        const float* __restrict__ Wlv, const float* __restrict__ blv,
        const float* __restrict__ eps, float* __restrict__ z,
        float* __restrict__ out) {
    __shared__ float As[16][68];
    __shared__ float Bm[16][68];
    __shared__ float Bl[16][68];
    const int tid = threadIdx.x;
    const int n0 = blockIdx.x * 64;
    const int m0 = blockIdx.y * 64;
    const int trow = tid >> 4;
    const int tcol = tid & 15;
    const int lm = tid >> 2;
    const int lk = (tid & 3) * 4;

    ull am[4][2], al[4][2];
    #pragma unroll
    for (int r = 0; r < 4; r++) { am[r][0]=0ull; am[r][1]=0ull; al[r][0]=0ull; al[r][1]=0ull; }

    for (int kk = 0; kk < GH; kk += 16) {
        float4 va = *(const float4*)&A[(size_t)(m0 + lm) * GH + kk + lk];
        float4 vm = *(const float4*)&Wmu[(size_t)(n0 + lm) * GH + kk + lk];
        float4 vl = *(const float4*)&Wlv[(size_t)(n0 + lm) * GH + kk + lk];
        As[lk+0][lm] = va.x; As[lk+1][lm] = va.y; As[lk+2][lm] = va.z; As[lk+3][lm] = va.w;
        Bm[lk+0][lm] = vm.x; Bm[lk+1][lm] = vm.y; Bm[lk+2][lm] = vm.z; Bm[lk+3][lm] = vm.w;
        Bl[lk+0][lm] = vl.x; Bl[lk+1][lm] = vl.y; Bl[lk+2][lm] = vl.z; Bl[lk+3][lm] = vl.w;
        __syncthreads();
        #pragma unroll
        for (int k = 0; k < 16; k++) {
            float4 a = *(const float4*)&As[k][trow * 4];
            const ull* bmp = (const ull*)&Bm[k][tcol * 4];
            const ull* blp = (const ull*)&Bl[k][tcol * 4];
            ull bm0 = bmp[0], bm1 = bmp[1], bl0 = blp[0], bl1 = blp[1];
            ull a0 = pk2(a.x, a.x), a1 = pk2(a.y, a.y);
            ull a2 = pk2(a.z, a.z), a3 = pk2(a.w, a.w);
            fma2(am[0][0], a0, bm0); fma2(am[0][1], a0, bm1);
            fma2(am[1][0], a1, bm0); fma2(am[1][1], a1, bm1);
            fma2(am[2][0], a2, bm0); fma2(am[2][1], a2, bm1);
            fma2(am[3][0], a3, bm0); fma2(am[3][1], a3, bm1);
            fma2(al[0][0], a0, bl0); fma2(al[0][1], a0, bl1);
            fma2(al[1][0], a1, bl0); fma2(al[1][1], a1, bl1);
            fma2(al[2][0], a2, bl0); fma2(al[2][1], a2, bl1);
            fma2(al[3][0], a3, bl0); fma2(al[3][1], a3, bl1);
        }
        __syncthreads();
    }

    #pragma unroll
    for (int r = 0; r < 4; r++) {
        int m = m0 + trow * 4 + r;
        int n = n0 + tcol * 4;
        size_t idx = (size_t)m * GH + n;
        float2 m0v = unpk2(am[r][0]);
        float2 m1v = unpk2(am[r][1]);
        float2 l0v = unpk2(al[r][0]);
        float2 l1v = unpk2(al[r][1]);
        float mu0 = m0v.x + bmu[n+0], mu1 = m0v.y + bmu[n+1];
        float mu2 = m1v.x + bmu[n+2], mu3 = m1v.y + bmu[n+3];
        float lv0 = l0v.x + blv[n+0], lv1 = l0v.y + blv[n+1];
        float lv2 = l1v.x + blv[n+2], lv3 = l1v.y + blv[n+3];
        float4 ev = *(const float4*)&eps[idx];
        *(float4*)&out[OFF_MU + idx] = make_float4(mu0, mu1, mu2, mu3);
        *(float4*)&out[OFF_LV + idx] = make_float4(lv0, lv1, lv2, lv3);
        *(float4*)&z[idx] = make_float4(mu0 + ev.x * expf(0.5f * lv0),
                                        mu1 + ev.y * expf(0.5f * lv1),
                                        mu2 + ev.z * expf(0.5f * lv2),
                                        mu3 + ev.w * expf(0.5f * lv3));
    }
}

// ============================================================================
// GRU recurrence: 128 CTAs x 384 thr, 2 rows/CTA, register weights + f32x2
// ============================================================================
__global__ __launch_bounds__(384, 1) void gru_kernel(const float* __restrict__ xp,
        const float* __restrict__ Whh, const float* __restrict__ bhh,
        float* __restrict__ h2all) {
    __shared__ __align__(16) float h_a[128];
    __shared__ __align__(16) float h_b[128];
    __shared__ float hp_s[768];
    __shared__ float xp_s[768];
    const int j = threadIdx.x;
    const int row0 = blockIdx.x * 2;

    ull w2[64];
    #pragma unroll
    for (int kq = 0; kq < 32; kq++) {
        float4 v = *(const float4*)&Whh[(size_t)j * GH + kq * 4];
        w2[2*kq+0] = pk2(v.x, v.y);
        w2[2*kq+1] = pk2(v.z, v.w);
    }
    const float bh = bhh[j];
    xp_s[j]       = xp[(size_t)row0 * 384 + j];
    xp_s[384 + j] = xp[(size_t)(row0 + 1) * 384 + j];
    if (j < 128) { h_a[j] = 0.0f; h_b[j] = 0.0f; }
    __syncthreads();

    for (int t = 0; t < SEQ; t++) {
        ull accA = 0ull, accB = 0ull;
        #pragma unroll
        for (int kq = 0; kq < 32; kq++) {
            ulonglong2 ha = *(const ulonglong2*)&h_a[kq * 4];
            ulonglong2 hb = *(const ulonglong2*)&h_b[kq * 4];
            fma2(accA, w2[2*kq+0], ha.x);
            fma2(accA, w2[2*kq+1], ha.y);
            fma2(accB, w2[2*kq+0], hb.x);
            fma2(accB, w2[2*kq+1], hb.y);
        }
        float2 pa = unpk2(accA);
        float2 pb = unpk2(accB);
        hp_s[j]       = pa.x + pa.y + bh;
        hp_s[384 + j] = pb.x + pb.y + bh;
        __syncthreads();
        if (j < 256) {
            int r = j >> 7, u = j & 127;
            const float* hp = hp_s + r * 384;
            const float* xq = xp_s + r * 384;
            float rg = 1.0f / (1.0f + expf(-(xq[u]       + hp[u])));
            float zg = 1.0f / (1.0f + expf(-(xq[128 + u] + hp[128 + u])));
            float nn = tanhf(xq[256 + u] + rg * hp[256 + u]);
            float hold = r ? h_b[u] : h_a[u];
            float hnew = (1.0f - zg) * nn + zg * hold;
            if (r) h_b[u] = hnew; else h_a[u] = hnew;
            h2all[((size_t)t * BATCH + row0 + r) * GH + u] = hnew;
        }
        __syncthreads();
    }
}

// ============================================================================
// final argmax reduce over 4 partials + one-hot write
// ============================================================================
__global__ __launch_bounds__(256) void argmax_final(const float2* __restrict__ amp,
                                                    float* __restrict__ out) {
    int row  = blockIdx.x * 8 + (threadIdx.x >> 5);
    int lane = threadIdx.x & 31;
    float best = -1e30f; int bi = 0x7fffffff;
    if (lane < 4) {
        float2 e = amp[(size_t)row * 4 + lane];
        best = e.x; bi = __float_as_int(e.y);
    }
    #pragma unroll
    for (int o = 1; o < 4; o <<= 1) {
        float ov = __shfl_xor_sync(0xffffffffu, best, o);
        int   oi = __shfl_xor_sync(0xffffffffu, bi, o);
        if (ov > best || (ov == best && oi < bi)) { best = ov; bi = oi; }
    }
    bi = __shfl_sync(0xffffffffu, bi, 0);
    int t = row >> 8, b = row & 255;
    float* op = out + (size_t)b * (SEQ * VOCAB) + (size_t)t * VOCAB;
    #pragma unroll
    for (int q = 0; q < 4; q++) {
        int c = lane * 16 + q * 4;
        *(float4*)&op[c] = make_float4(c == bi ? 1.f : 0.f, c + 1 == bi ? 1.f : 0.f,
                                       c + 2 == bi ? 1.f : 0.f, c + 3 == bi ? 1.f : 0.f);
    }
}

// ============================================================================
// launcher
// ============================================================================
extern "C" void kernel_launch(void* const* d_in, const int* in_sizes, int n_in,
                              void* d_out, int out_size) {
    (void)in_sizes; (void)n_in; (void)out_size;
    const float* x    = (const float*)d_in[0];
    const float* eps  = (const float*)d_in[1];
    const float* W0   = (const float*)d_in[2];
    const float* b0   = (const float*)d_in[3];
    const float* g0   = (const float*)d_in[4];
    const float* be0  = (const float*)d_in[5];
    const float* W1   = (const float*)d_in[6];
    const float* b1   = (const float*)d_in[7];
    const float* g1   = (const float*)d_in[8];
    const float* be1  = (const float*)d_in[9];
    const float* W2   = (const float*)d_in[10];
    const float* b2   = (const float*)d_in[11];
    const float* g2   = (const float*)d_in[12];
    const float* be2  = (const float*)d_in[13];
    const float* Wout = (const float*)d_in[14];
    const float* bout = (const float*)d_in[15];
    const float* Wmu  = (const float*)d_in[16];
    const float* bmu  = (const float*)d_in[17];
    const float* Wlv  = (const float*)d_in[18];
    const float* blv  = (const float*)d_in[19];
    const float* Wih  = (const float*)d_in[20];
    const float* bih  = (const float*)d_in[21];
    const float* Whh  = (const float*)d_in[22];
    const float* bhh  = (const float*)d_in[23];
    const float* Wfc  = (const float*)d_in[24];
    const float* bfc  = (const float*)d_in[25];
    float* out = (float*)d_out;

    float* S = nullptr;
    cudaGetSymbolAddress((void**)&S, g_scratch);

    cudaFuncSetAttribute(gemm_mma, cudaFuncAttributeMaxDynamicSharedMemorySize, MMA_SMEM);
    cudaFuncSetAttribute(gemm_logits, cudaFuncAttributeMaxDynamicSharedMemorySize, LOGITS_SMEM);

    // --- encoder layer 0: fp16-split mma, split-K=9 (144 CTAs = 1 wave) ---
    gemm_mma<<<dim3(8, 2, GSPLITS), 256, MMA_SMEM>>>(x, W0, nullptr, S + S_WS,
        K0, N0, TCHUNKS0, GSPLITS, (size_t)BATCH * N0,
        nullptr, nullptr, nullptr, nullptr, 0);
    reduce_gen<<<256, 256>>>(S + S_WS, b0, S + S_H0, GSPLITS, BATCH * N0, N0 - 1, 0);
    bn_part<<<dim3(4, NPARTS), 256>>>(S + S_H0, S + S_BNP, S + S_BNQ, 1024);

    // --- encoder layer 1: 1024 -> 512, split-K=16 (BN0+lrelu finalized in-kernel) ---
    gemm_mma<<<dim3(4, 2, 16), 256, MMA_SMEM>>>(S + S_H0, W1, nullptr, S + S_WS,
        1024, 512, 32, 16, (size_t)BATCH * 512,
        S + S_BNP, S + S_BNQ, g0, be0, 0);
    reduce_gen<<<128, 256>>>(S + S_WS, b1, S + S_H1, 16, BATCH * 512, 511, 0);
    bn_part<<<dim3(2, NPARTS), 256>>>(S + S_H1, S + S_BNP, S + S_BNQ, 512);

    // --- encoder layer 2: 512 -> 256, split-K=8 (BN1 fused) ---
    gemm_mma<<<dim3(2, 2, 8), 256, MMA_SMEM>>>(S + S_H1, W2, nullptr, S + S_WS,
        512, 256, 16, 8, (size_t)BATCH * 256,
        S + S_BNP, S + S_BNQ, g1, be1, 0);
    reduce_gen<<<64, 256>>>(S + S_WS, b2, S + S_H2B, 8, BATCH * 256, 255, 0);
    bn_part<<<dim3(1, NPARTS), 256>>>(S + S_H2B, S + S_BNP, S + S_BNQ, 256);

    // --- out layer: 256 -> 128, split-K=8 (BN2 fused), relu in reduce ---
    gemm_mma<<<dim3(1, 2, 8), 256, MMA_SMEM>>>(S + S_H2B, Wout, nullptr, S + S_WS,
        256, 128, 8, 8, (size_t)BATCH * 128,
        S + S_BNP, S + S_BNQ, g2, be2, 0);
    reduce_gen<<<32, 256>>>(S + S_WS, bout, S + S_HENC, 8, BATCH * 128, 127, 1);

    // --- mu & lv & reparameterize in ONE kernel (writes out mu/lv + z) ---
    gemm_mulv<<<dim3(2, 4), 256>>>(S + S_HENC, Wmu, bmu, Wlv, blv, eps, S + S_Z, out);

    // --- GRU input projection ---
    gemm_kernel<<<dim3(6, 4), 256>>>(S + S_Z, Wih, bih, S + S_XP, 256, 384, 128);

    // --- GRU recurrence ---
    gru_kernel<<<128, 384>>>(S + S_XP, Whh, bhh, S + S_H2ALL);

    // --- persistent logits GEMM with fused bias+argmax (1 wave) ---
    gemm_logits<<<dim3(4, 32), 256, LOGITS_SMEM>>>(S + S_H2ALL, Wfc, bfc,
                                                   (float2*)(S + S_AMP));
    argmax_final<<<4096, 256>>>((const float2*)(S + S_AMP), out);
}